// round 4
// baseline (speedup 1.0000x reference)
#include <cuda_runtime.h>
#include <math.h>
#include <stdint.h>

// Problem constants (fixed by reference setup_inputs)
#define BATCH 32
#define SQ 512
#define SK 512
#define DIM 512
#define DIM2 1024
#define SCALE 0.044194173824159216f  // 1/sqrt(512)

// Tiling
#define BM 128
#define BN 128
#define BK 16
#define AS_STRIDE 20     // [m][k] 16 + 4 pad
#define BS_STRIDE 20     // NT: [n][k]
#define BS_STRIDE_NN 136 // NN: [k][n] 128 + 8 pad

// Scratch: attention context (B, SQ, DIM). Device global => no allocation.
__device__ float g_ctx[BATCH * SQ * DIM];

__device__ __forceinline__ uint32_t f2tf32(float f) {
    uint32_t r;
    asm("cvt.rna.tf32.f32 %0, %1;" : "=r"(r) : "f"(f));
    return r;
}

__device__ __forceinline__ void mma_tf32(float c[4],
    uint32_t a0, uint32_t a1, uint32_t a2, uint32_t a3,
    uint32_t b0, uint32_t b1)
{
    asm volatile(
        "mma.sync.aligned.m16n8k8.row.col.f32.tf32.tf32.f32 "
        "{%0,%1,%2,%3}, {%4,%5,%6,%7}, {%8,%9}, {%0,%1,%2,%3};"
        : "+f"(c[0]), "+f"(c[1]), "+f"(c[2]), "+f"(c[3])
        : "r"(a0), "r"(a1), "r"(a2), "r"(a3), "r"(b0), "r"(b1));
}

// ---------------------------------------------------------------------------
// Kernel 1: scores S[b,q,k] = SCALE * Q[b,q,:] . E[b,k,:]   (NT, K=512)
// Double-buffered smem, 1 sync per K-panel.
// ---------------------------------------------------------------------------
__global__ __launch_bounds__(256, 1) void gemm_scores_tc(
    const float* __restrict__ Q, const float* __restrict__ E,
    float* __restrict__ S)
{
    __shared__ uint32_t As[2][BM * AS_STRIDE];
    __shared__ uint32_t Bs[2][BN * BS_STRIDE];

    const int b = blockIdx.z;
    const float* Qb = Q + (size_t)b * SQ * DIM;
    const float* Eb = E + (size_t)b * SK * DIM;
    float* Sb = S + (size_t)b * SQ * SK;

    const int mBase = blockIdx.y * BM;
    const int nBase = blockIdx.x * BN;
    const int tid = threadIdx.x;
    const int lane = tid & 31;
    const int w = tid >> 5;
    const int m0 = (w & 3) * 32;
    const int n0 = (w >> 2) * 64;

    float acc[2][8][4];
    #pragma unroll
    for (int i = 0; i < 2; i++)
        #pragma unroll
        for (int j = 0; j < 8; j++)
            #pragma unroll
            for (int q = 0; q < 4; q++) acc[i][j][q] = 0.f;

    const int ldRow = tid >> 2;        // 0..63 (+64 for pass 1)
    const int ldCol = (tid & 3) * 4;   // 0,4,8,12

    float4 stA[2], stB[2];
    #pragma unroll
    for (int p = 0; p < 2; p++) {
        int row = ldRow + p * 64;
        stA[p] = *(const float4*)(Qb + (size_t)(mBase + row) * DIM + ldCol);
        stB[p] = *(const float4*)(Eb + (size_t)(nBase + row) * DIM + ldCol);
    }
    #pragma unroll
    for (int p = 0; p < 2; p++) {
        int row = ldRow + p * 64;
        uint32_t* pa = &As[0][row * AS_STRIDE + ldCol];
        pa[0] = f2tf32(stA[p].x); pa[1] = f2tf32(stA[p].y);
        pa[2] = f2tf32(stA[p].z); pa[3] = f2tf32(stA[p].w);
        uint32_t* pb = &Bs[0][row * BS_STRIDE + ldCol];
        pb[0] = f2tf32(stB[p].x); pb[1] = f2tf32(stB[p].y);
        pb[2] = f2tf32(stB[p].z); pb[3] = f2tf32(stB[p].w);
    }
    __syncthreads();

    int cur = 0;
    for (int k0 = 0; k0 < DIM; k0 += BK) {
        const bool hasNext = (k0 + BK) < DIM;
        if (hasNext) {
            #pragma unroll
            for (int p = 0; p < 2; p++) {
                int row = ldRow + p * 64;
                stA[p] = *(const float4*)(Qb + (size_t)(mBase + row) * DIM + k0 + BK + ldCol);
                stB[p] = *(const float4*)(Eb + (size_t)(nBase + row) * DIM + k0 + BK + ldCol);
            }
        }

        #pragma unroll
        for (int kc = 0; kc < BK; kc += 8) {
            uint32_t af[2][4], bf[8][2];
            #pragma unroll
            for (int mi = 0; mi < 2; mi++) {
                int r = m0 + mi * 16 + (lane >> 2);
                int c = kc + (lane & 3);
                af[mi][0] = As[cur][r * AS_STRIDE + c];
                af[mi][1] = As[cur][(r + 8) * AS_STRIDE + c];
                af[mi][2] = As[cur][r * AS_STRIDE + c + 4];
                af[mi][3] = As[cur][(r + 8) * AS_STRIDE + c + 4];
            }
            #pragma unroll
            for (int nj = 0; nj < 8; nj++) {
                int r = n0 + nj * 8 + (lane >> 2);
                int c = kc + (lane & 3);
                bf[nj][0] = Bs[cur][r * BS_STRIDE + c];
                bf[nj][1] = Bs[cur][r * BS_STRIDE + c + 4];
            }
            #pragma unroll
            for (int mi = 0; mi < 2; mi++)
                #pragma unroll
                for (int nj = 0; nj < 8; nj++)
                    mma_tf32(acc[mi][nj], af[mi][0], af[mi][1], af[mi][2], af[mi][3],
                             bf[nj][0], bf[nj][1]);
        }

        if (hasNext) {
            int nxt = cur ^ 1;
            #pragma unroll
            for (int p = 0; p < 2; p++) {
                int row = ldRow + p * 64;
                uint32_t* pa = &As[nxt][row * AS_STRIDE + ldCol];
                pa[0] = f2tf32(stA[p].x); pa[1] = f2tf32(stA[p].y);
                pa[2] = f2tf32(stA[p].z); pa[3] = f2tf32(stA[p].w);
                uint32_t* pb = &Bs[nxt][row * BS_STRIDE + ldCol];
                pb[0] = f2tf32(stB[p].x); pb[1] = f2tf32(stB[p].y);
                pb[2] = f2tf32(stB[p].z); pb[3] = f2tf32(stB[p].w);
            }
        }
        __syncthreads();
        cur ^= 1;
    }

    #pragma unroll
    for (int mi = 0; mi < 2; mi++) {
        #pragma unroll
        for (int nj = 0; nj < 8; nj++) {
            int row = mBase + m0 + mi * 16 + (lane >> 2);
            int col = nBase + n0 + nj * 8 + (lane & 3) * 2;
            float2 v0 = make_float2(acc[mi][nj][0] * SCALE, acc[mi][nj][1] * SCALE);
            float2 v1 = make_float2(acc[mi][nj][2] * SCALE, acc[mi][nj][3] * SCALE);
            *(float2*)(Sb + (size_t)row * SK + col) = v0;
            *(float2*)(Sb + (size_t)(row + 8) * SK + col) = v1;
        }
    }
}

// ---------------------------------------------------------------------------
// Kernel 2: in-place row softmax over SK=512 columns.
// ---------------------------------------------------------------------------
__global__ __launch_bounds__(256) void softmax_rows(float* __restrict__ S)
{
    const int row = blockIdx.x;
    float* p = S + (size_t)row * SK;
    const int tid = threadIdx.x;

    float v0 = p[tid];
    float v1 = p[tid + 256];

    __shared__ float red[8];

    float m = fmaxf(v0, v1);
    #pragma unroll
    for (int o = 16; o > 0; o >>= 1) m = fmaxf(m, __shfl_xor_sync(0xffffffffu, m, o));
    if ((tid & 31) == 0) red[tid >> 5] = m;
    __syncthreads();
    m = red[0];
    #pragma unroll
    for (int i = 1; i < 8; i++) m = fmaxf(m, red[i]);

    float e0 = __expf(v0 - m);
    float e1 = __expf(v1 - m);

    float s = e0 + e1;
    #pragma unroll
    for (int o = 16; o > 0; o >>= 1) s += __shfl_xor_sync(0xffffffffu, s, o);
    __syncthreads();
    if ((tid & 31) == 0) red[tid >> 5] = s;
    __syncthreads();
    s = red[0];
    #pragma unroll
    for (int i = 1; i < 8; i++) s += red[i];

    float inv = 1.0f / s;
    p[tid] = e0 * inv;
    p[tid + 256] = e1 * inv;
}

// ---------------------------------------------------------------------------
// Kernel 3: context C[b,q,d] = sum_k A[b,q,k] * E[b,k,d]   (NN, K=512)
// ---------------------------------------------------------------------------
__global__ __launch_bounds__(256, 1) void gemm_ctx_tc(
    const float* __restrict__ A, const float* __restrict__ E,
    float* __restrict__ C)
{
    __shared__ uint32_t As[2][BM * AS_STRIDE];     // [m][k]
    __shared__ uint32_t Bs[2][BK * BS_STRIDE_NN];  // [k][n]

    const int b = blockIdx.z;
    const float* Ab = A + (size_t)b * SQ * SK;
    const float* Eb = E + (size_t)b * SK * DIM;
    float* Cb = C + (size_t)b * SQ * DIM;

    const int mBase = blockIdx.y * BM;
    const int nBase = blockIdx.x * BN;
    const int tid = threadIdx.x;
    const int lane = tid & 31;
    const int w = tid >> 5;
    const int m0 = (w & 3) * 32;
    const int n0 = (w >> 2) * 64;

    float acc[2][8][4];
    #pragma unroll
    for (int i = 0; i < 2; i++)
        #pragma unroll
        for (int j = 0; j < 8; j++)
            #pragma unroll
            for (int q = 0; q < 4; q++) acc[i][j][q] = 0.f;

    const int ldRowA = tid >> 2;        // 0..63 (+64)
    const int ldColA = (tid & 3) * 4;
    const int ldRowB = tid >> 4;        // k row 0..15
    const int ldColB = (tid & 15) * 4;  // n col 0..60 (+64)

    float4 stA[2], stB[2];
    #pragma unroll
    for (int p = 0; p < 2; p++) {
        stA[p] = *(const float4*)(Ab + (size_t)(mBase + ldRowA + p * 64) * SK + ldColA);
        stB[p] = *(const float4*)(Eb + (size_t)ldRowB * DIM + nBase + ldColB + p * 64);
    }
    #pragma unroll
    for (int p = 0; p < 2; p++) {
        uint32_t* pa = &As[0][(ldRowA + p * 64) * AS_STRIDE + ldColA];
        pa[0] = f2tf32(stA[p].x); pa[1] = f2tf32(stA[p].y);
        pa[2] = f2tf32(stA[p].z); pa[3] = f2tf32(stA[p].w);
        uint32_t* pb = &Bs[0][ldRowB * BS_STRIDE_NN + ldColB + p * 64];
        pb[0] = f2tf32(stB[p].x); pb[1] = f2tf32(stB[p].y);
        pb[2] = f2tf32(stB[p].z); pb[3] = f2tf32(stB[p].w);
    }
    __syncthreads();

    int cur = 0;
    for (int k0 = 0; k0 < SK; k0 += BK) {
        const bool hasNext = (k0 + BK) < SK;
        if (hasNext) {
            #pragma unroll
            for (int p = 0; p < 2; p++) {
                stA[p] = *(const float4*)(Ab + (size_t)(mBase + ldRowA + p * 64) * SK + k0 + BK + ldColA);
                stB[p] = *(const float4*)(Eb + (size_t)(k0 + BK + ldRowB) * DIM + nBase + ldColB + p * 64);
            }
        }

        #pragma unroll
        for (int kc = 0; kc < BK; kc += 8) {
            uint32_t af[2][4], bf[8][2];
            #pragma unroll
            for (int mi = 0; mi < 2; mi++) {
                int r = m0 + mi * 16 + (lane >> 2);
                int c = kc + (lane & 3);
                af[mi][0] = As[cur][r * AS_STRIDE + c];
                af[mi][1] = As[cur][(r + 8) * AS_STRIDE + c];
                af[mi][2] = As[cur][r * AS_STRIDE + c + 4];
                af[mi][3] = As[cur][(r + 8) * AS_STRIDE + c + 4];
            }
            #pragma unroll
            for (int nj = 0; nj < 8; nj++) {
                int n = n0 + nj * 8 + (lane >> 2);
                int k = kc + (lane & 3);
                bf[nj][0] = Bs[cur][k * BS_STRIDE_NN + n];
                bf[nj][1] = Bs[cur][(k + 4) * BS_STRIDE_NN + n];
            }
            #pragma unroll
            for (int mi = 0; mi < 2; mi++)
                #pragma unroll
                for (int nj = 0; nj < 8; nj++)
                    mma_tf32(acc[mi][nj], af[mi][0], af[mi][1], af[mi][2], af[mi][3],
                             bf[nj][0], bf[nj][1]);
        }

        if (hasNext) {
            int nxt = cur ^ 1;
            #pragma unroll
            for (int p = 0; p < 2; p++) {
                uint32_t* pa = &As[nxt][(ldRowA + p * 64) * AS_STRIDE + ldColA];
                pa[0] = f2tf32(stA[p].x); pa[1] = f2tf32(stA[p].y);
                pa[2] = f2tf32(stA[p].z); pa[3] = f2tf32(stA[p].w);
                uint32_t* pb = &Bs[nxt][ldRowB * BS_STRIDE_NN + ldColB + p * 64];
                pb[0] = f2tf32(stB[p].x); pb[1] = f2tf32(stB[p].y);
                pb[2] = f2tf32(stB[p].z); pb[3] = f2tf32(stB[p].w);
            }
        }
        __syncthreads();
        cur ^= 1;
    }

    #pragma unroll
    for (int mi = 0; mi < 2; mi++) {
        #pragma unroll
        for (int nj = 0; nj < 8; nj++) {
            int row = mBase + m0 + mi * 16 + (lane >> 2);
            int col = nBase + n0 + nj * 8 + (lane & 3) * 2;
            *(float2*)(Cb + (size_t)row * DIM + col) = make_float2(acc[mi][nj][0], acc[mi][nj][1]);
            *(float2*)(Cb + (size_t)(row + 8) * DIM + col) = make_float2(acc[mi][nj][2], acc[mi][nj][3]);
        }
    }
}

// ---------------------------------------------------------------------------
// Kernel 4: out = tanh([Q,ctx] @ W^T + b) * mask   (NT, K=1024)
// ---------------------------------------------------------------------------
__global__ __launch_bounds__(256, 1) void gemm_out_tc(
    const float* __restrict__ Q, const float* __restrict__ W,
    const float* __restrict__ bias, const float* __restrict__ mask,
    float* __restrict__ O)
{
    __shared__ uint32_t As[2][BM * AS_STRIDE];
    __shared__ uint32_t Bs[2][BN * BS_STRIDE];

    const int b = blockIdx.z;
    const float* Qb = Q + (size_t)b * SQ * DIM;
    const float* Cb = g_ctx + (size_t)b * SQ * DIM;
    float* Ob = O + (size_t)b * SQ * DIM;

    const int mBase = blockIdx.y * BM;
    const int nBase = blockIdx.x * BN;
    const int tid = threadIdx.x;
    const int lane = tid & 31;
    const int w = tid >> 5;
    const int m0 = (w & 3) * 32;
    const int n0 = (w >> 2) * 64;

    float acc[2][8][4];
    #pragma unroll
    for (int i = 0; i < 2; i++)
        #pragma unroll
        for (int j = 0; j < 8; j++)
            #pragma unroll
            for (int q = 0; q < 4; q++) acc[i][j][q] = 0.f;

    const int ldRow = tid >> 2;
    const int ldCol = (tid & 3) * 4;

    float4 stA[2], stB[2];
    #pragma unroll
    for (int p = 0; p < 2; p++) {
        int row = ldRow + p * 64;
        stA[p] = *(const float4*)(Qb + (size_t)(mBase + row) * DIM + ldCol);
        stB[p] = *(const float4*)(W + (size_t)(nBase + row) * DIM2 + ldCol);
    }
    #pragma unroll
    for (int p = 0; p < 2; p++) {
        int row = ldRow + p * 64;
        uint32_t* pa = &As[0][row * AS_STRIDE + ldCol];
        pa[0] = f2tf32(stA[p].x); pa[1] = f2tf32(stA[p].y);
        pa[2] = f2tf32(stA[p].z); pa[3] = f2tf32(stA[p].w);
        uint32_t* pb = &Bs[0][row * BS_STRIDE + ldCol];
        pb[0] = f2tf32(stB[p].x); pb[1] = f2tf32(stB[p].y);
        pb[2] = f2tf32(stB[p].z); pb[3] = f2tf32(stB[p].w);
    }
    __syncthreads();

    int cur = 0;
    for (int k0 = 0; k0 < DIM2; k0 += BK) {
        const bool hasNext = (k0 + BK) < DIM2;
        if (hasNext) {
            int kn = k0 + BK;
            const float* Asrc = (kn < DIM) ? Qb : Cb;
            int kk = kn & (DIM - 1);
            #pragma unroll
            for (int p = 0; p < 2; p++) {
                int row = ldRow + p * 64;
                stA[p] = *(const float4*)(Asrc + (size_t)(mBase + row) * DIM + kk + ldCol);
                stB[p] = *(const float4*)(W + (size_t)(nBase + row) * DIM2 + kn + ldCol);
            }
        }

        #pragma unroll
        for (int kc = 0; kc < BK; kc += 8) {
            uint32_t af[2][4], bf[8][2];
            #pragma unroll
            for (int mi = 0; mi < 2; mi++) {
                int r = m0 + mi * 16 + (lane >> 2);
                int c = kc + (lane & 3);
                af[mi][0] = As[cur][r * AS_STRIDE + c];
                af[mi][1] = As[cur][(r + 8) * AS_STRIDE + c];
                af[mi][2] = As[cur][r * AS_STRIDE + c + 4];
                af[mi][3] = As[cur][(r + 8) * AS_STRIDE + c + 4];
            }
            #pragma unroll
            for (int nj = 0; nj < 8; nj++) {
                int r = n0 + nj * 8 + (lane >> 2);
                int c = kc + (lane & 3);
                bf[nj][0] = Bs[cur][r * BS_STRIDE + c];
                bf[nj][1] = Bs[cur][r * BS_STRIDE + c + 4];
            }
            #pragma unroll
            for (int mi = 0; mi < 2; mi++)
                #pragma unroll
                for (int nj = 0; nj < 8; nj++)
                    mma_tf32(acc[mi][nj], af[mi][0], af[mi][1], af[mi][2], af[mi][3],
                             bf[nj][0], bf[nj][1]);
        }

        if (hasNext) {
            int nxt = cur ^ 1;
            #pragma unroll
            for (int p = 0; p < 2; p++) {
                int row = ldRow + p * 64;
                uint32_t* pa = &As[nxt][row * AS_STRIDE + ldCol];
                pa[0] = f2tf32(stA[p].x); pa[1] = f2tf32(stA[p].y);
                pa[2] = f2tf32(stA[p].z); pa[3] = f2tf32(stA[p].w);
                uint32_t* pb = &Bs[nxt][row * BS_STRIDE + ldCol];
                pb[0] = f2tf32(stB[p].x); pb[1] = f2tf32(stB[p].y);
                pb[2] = f2tf32(stB[p].z); pb[3] = f2tf32(stB[p].w);
            }
        }
        __syncthreads();
        cur ^= 1;
    }

    #pragma unroll
    for (int mi = 0; mi < 2; mi++) {
        #pragma unroll
        for (int nj = 0; nj < 8; nj++) {
            int row = mBase + m0 + mi * 16 + (lane >> 2);
            int col = nBase + n0 + nj * 8 + (lane & 3) * 2;
            float b0 = bias[col], b1 = bias[col + 1];
            float mk0 = mask[(size_t)b * SQ + row];
            float mk1 = mask[(size_t)b * SQ + row + 8];
            float2 v0 = make_float2(tanhf(acc[mi][nj][0] + b0) * mk0,
                                    tanhf(acc[mi][nj][1] + b1) * mk0);
            float2 v1 = make_float2(tanhf(acc[mi][nj][2] + b0) * mk1,
                                    tanhf(acc[mi][nj][3] + b1) * mk1);
            *(float2*)(Ob + (size_t)row * DIM + col) = v0;
            *(float2*)(Ob + (size_t)(row + 8) * DIM + col) = v1;
        }
    }
}

// ---------------------------------------------------------------------------
extern "C" void kernel_launch(void* const* d_in, const int* in_sizes, int n_in,
                              void* d_out, int out_size)
{
    const float* Q    = (const float*)d_in[0];
    const float* E    = (const float*)d_in[1];
    const float* mask = (const float*)d_in[2];
    const float* W    = (const float*)d_in[3];
    const float* bias = (const float*)d_in[4];

    float* out = (float*)d_out;
    float* out_masked  = out;
    float* out_weights = out + (size_t)BATCH * SQ * DIM;

    float* ctx;
    cudaGetSymbolAddress((void**)&ctx, g_ctx);

    dim3 blk(256);
    dim3 grid(SK / BN, SQ / BM, BATCH);   // (4,4,32)

    gemm_scores_tc<<<grid, blk>>>(Q, E, out_weights);
    softmax_rows<<<BATCH * SQ, 256>>>(out_weights);
    gemm_ctx_tc<<<grid, blk>>>(out_weights, E, ctx);
    gemm_out_tc<<<grid, blk>>>(Q, W, bias, mask, out_masked);
}

// round 5
// speedup vs baseline: 1.1974x; 1.1974x over previous
#include <cuda_runtime.h>
#include <math.h>
#include <stdint.h>

#define BATCH 32
#define SQ 512
#define SK 512
#define DIM 512
#define DIM2 1024
#define SCALE 0.044194173824159216f  // 1/sqrt(512)

#define BM 128
#define BN 128
#define BK 16
#define ASTR 20    // A smem row stride (words): 16 + 4 pad
#define BSTR 20    // B smem row stride (NT)
#define BSTR_NN 136 // B smem row stride (NN): 128 + 8 pad

// tf32-converted operand copies + scratch (device globals: no allocation)
__device__ uint32_t g_Qt[BATCH * SQ * DIM];    // tf32(Q)
__device__ uint32_t g_Et[BATCH * SK * DIM];    // tf32(E)
__device__ uint32_t g_Wt[DIM * DIM2];          // tf32(W)
__device__ uint32_t g_At[BATCH * SQ * SK];     // tf32(softmax weights)
__device__ uint32_t g_Ct[BATCH * SQ * DIM];    // tf32(context)

__device__ __forceinline__ uint32_t f2tf32(float f) {
    uint32_t r;
    asm("cvt.rna.tf32.f32 %0, %1;" : "=r"(r) : "f"(f));
    return r;
}

__device__ __forceinline__ void cp16(uint32_t smem_dst, const void* gsrc) {
    asm volatile("cp.async.cg.shared.global [%0], [%1], 16;" :: "r"(smem_dst), "l"(gsrc));
}
__device__ __forceinline__ void cp_commit() {
    asm volatile("cp.async.commit_group;");
}
template<int N>
__device__ __forceinline__ void cp_wait() {
    asm volatile("cp.async.wait_group %0;" :: "n"(N));
}

__device__ __forceinline__ void mma_tf32(float c[4],
    uint32_t a0, uint32_t a1, uint32_t a2, uint32_t a3,
    uint32_t b0, uint32_t b1)
{
    asm volatile(
        "mma.sync.aligned.m16n8k8.row.col.f32.tf32.tf32.f32 "
        "{%0,%1,%2,%3}, {%4,%5,%6,%7}, {%8,%9}, {%0,%1,%2,%3};"
        : "+f"(c[0]), "+f"(c[1]), "+f"(c[2]), "+f"(c[3])
        : "r"(a0), "r"(a1), "r"(a2), "r"(a3), "r"(b0), "r"(b1));
}

// ---------------------------------------------------------------------------
// elementwise f32 -> tf32 convert (vectorized)
// ---------------------------------------------------------------------------
__global__ __launch_bounds__(256) void cvt_tf32_kernel(
    const float4* __restrict__ in, uint4* __restrict__ out, int n4)
{
    int i = blockIdx.x * 256 + threadIdx.x;
    if (i < n4) {
        float4 v = in[i];
        uint4 o;
        o.x = f2tf32(v.x); o.y = f2tf32(v.y);
        o.z = f2tf32(v.z); o.w = f2tf32(v.w);
        out[i] = o;
    }
}

// ---------------------------------------------------------------------------
// Kernel 1: scores S = SCALE * Qt . Et^T   (NT, K=512) -> fp32
// 2-stage cp.async pipeline, 1 sync per panel, 2 CTAs/SM.
// ---------------------------------------------------------------------------
__global__ __launch_bounds__(256, 2) void gemm_scores_tc(
    const uint32_t* __restrict__ Qt, const uint32_t* __restrict__ Et,
    float* __restrict__ S)
{
    __shared__ uint32_t As[2][BM * ASTR];
    __shared__ uint32_t Bs[2][BN * BSTR];

    const int b = blockIdx.z;
    const uint32_t* Qb = Qt + (size_t)b * SQ * DIM;
    const uint32_t* Eb = Et + (size_t)b * SK * DIM;
    float* Sb = S + (size_t)b * SQ * SK;

    const int mBase = blockIdx.y * BM;
    const int nBase = blockIdx.x * BN;
    const int tid = threadIdx.x;
    const int lane = tid & 31;
    const int w = tid >> 5;
    const int m0 = (w & 3) * 32;
    const int n0 = (w >> 2) * 64;

    float acc[2][8][4];
    #pragma unroll
    for (int i = 0; i < 2; i++)
        #pragma unroll
        for (int j = 0; j < 8; j++)
            #pragma unroll
            for (int q = 0; q < 4; q++) acc[i][j][q] = 0.f;

    const int ldr = tid >> 2;        // 0..63
    const int ldc = (tid & 3) * 4;   // 0,4,8,12 (words)

    const uint32_t sA = (uint32_t)__cvta_generic_to_shared(&As[0][0]);
    const uint32_t sB = (uint32_t)__cvta_generic_to_shared(&Bs[0][0]);
    const uint32_t stageA = BM * ASTR * 4;
    const uint32_t stageB = BN * BSTR * 4;
    const uint32_t dA0 = (ldr * ASTR + ldc) * 4;
    const uint32_t dA1 = ((ldr + 64) * ASTR + ldc) * 4;
    const uint32_t dB0 = (ldr * BSTR + ldc) * 4;
    const uint32_t dB1 = ((ldr + 64) * BSTR + ldc) * 4;

    // prologue: issue stage 0
    {
        cp16(sA + dA0, Qb + (size_t)(mBase + ldr) * DIM + ldc);
        cp16(sA + dA1, Qb + (size_t)(mBase + ldr + 64) * DIM + ldc);
        cp16(sB + dB0, Eb + (size_t)(nBase + ldr) * DIM + ldc);
        cp16(sB + dB1, Eb + (size_t)(nBase + ldr + 64) * DIM + ldc);
        cp_commit();
    }

    const int NP = DIM / BK;  // 32
    for (int i = 0; i < NP; i++) {
        cp_wait<0>();
        __syncthreads();
        if (i + 1 < NP) {
            int k = (i + 1) * BK;
            uint32_t bo = ((i + 1) & 1) ? 1u : 0u;
            cp16(sA + bo * stageA + dA0, Qb + (size_t)(mBase + ldr) * DIM + k + ldc);
            cp16(sA + bo * stageA + dA1, Qb + (size_t)(mBase + ldr + 64) * DIM + k + ldc);
            cp16(sB + bo * stageB + dB0, Eb + (size_t)(nBase + ldr) * DIM + k + ldc);
            cp16(sB + bo * stageB + dB1, Eb + (size_t)(nBase + ldr + 64) * DIM + k + ldc);
            cp_commit();
        }
        const uint32_t* Ac = As[i & 1];
        const uint32_t* Bc = Bs[i & 1];
        #pragma unroll
        for (int kc = 0; kc < BK; kc += 8) {
            uint32_t af[2][4], bf[8][2];
            #pragma unroll
            for (int mi = 0; mi < 2; mi++) {
                int r = m0 + mi * 16 + (lane >> 2);
                int c = kc + (lane & 3);
                af[mi][0] = Ac[r * ASTR + c];
                af[mi][1] = Ac[(r + 8) * ASTR + c];
                af[mi][2] = Ac[r * ASTR + c + 4];
                af[mi][3] = Ac[(r + 8) * ASTR + c + 4];
            }
            #pragma unroll
            for (int nj = 0; nj < 8; nj++) {
                int r = n0 + nj * 8 + (lane >> 2);
                int c = kc + (lane & 3);
                bf[nj][0] = Bc[r * BSTR + c];
                bf[nj][1] = Bc[r * BSTR + c + 4];
            }
            #pragma unroll
            for (int mi = 0; mi < 2; mi++)
                #pragma unroll
                for (int nj = 0; nj < 8; nj++)
                    mma_tf32(acc[mi][nj], af[mi][0], af[mi][1], af[mi][2], af[mi][3],
                             bf[nj][0], bf[nj][1]);
        }
    }

    #pragma unroll
    for (int mi = 0; mi < 2; mi++) {
        #pragma unroll
        for (int nj = 0; nj < 8; nj++) {
            int row = mBase + m0 + mi * 16 + (lane >> 2);
            int col = nBase + n0 + nj * 8 + (lane & 3) * 2;
            *(float2*)(Sb + (size_t)row * SK + col) =
                make_float2(acc[mi][nj][0] * SCALE, acc[mi][nj][1] * SCALE);
            *(float2*)(Sb + (size_t)(row + 8) * SK + col) =
                make_float2(acc[mi][nj][2] * SCALE, acc[mi][nj][3] * SCALE);
        }
    }
}

// ---------------------------------------------------------------------------
// Kernel 2: softmax rows; writes fp32 (output) + tf32 copy (for ctx GEMM)
// ---------------------------------------------------------------------------
__global__ __launch_bounds__(256) void softmax_rows(
    float* __restrict__ S, uint32_t* __restrict__ At)
{
    const int row = blockIdx.x;
    float* p = S + (size_t)row * SK;
    uint32_t* pt = At + (size_t)row * SK;
    const int tid = threadIdx.x;

    float v0 = p[tid];
    float v1 = p[tid + 256];

    __shared__ float red[8];

    float m = fmaxf(v0, v1);
    #pragma unroll
    for (int o = 16; o > 0; o >>= 1) m = fmaxf(m, __shfl_xor_sync(0xffffffffu, m, o));
    if ((tid & 31) == 0) red[tid >> 5] = m;
    __syncthreads();
    m = red[0];
    #pragma unroll
    for (int i = 1; i < 8; i++) m = fmaxf(m, red[i]);

    float e0 = __expf(v0 - m);
    float e1 = __expf(v1 - m);

    float s = e0 + e1;
    #pragma unroll
    for (int o = 16; o > 0; o >>= 1) s += __shfl_xor_sync(0xffffffffu, s, o);
    __syncthreads();
    if ((tid & 31) == 0) red[tid >> 5] = s;
    __syncthreads();
    s = red[0];
    #pragma unroll
    for (int i = 1; i < 8; i++) s += red[i];

    float inv = 1.0f / s;
    float w0 = e0 * inv, w1 = e1 * inv;
    p[tid] = w0;
    p[tid + 256] = w1;
    pt[tid] = f2tf32(w0);
    pt[tid + 256] = f2tf32(w1);
}

// ---------------------------------------------------------------------------
// Kernel 3: ctx = At . Et (NN, K=512) -> stores tf32 directly
// ---------------------------------------------------------------------------
__global__ __launch_bounds__(256, 2) void gemm_ctx_tc(
    const uint32_t* __restrict__ At, const uint32_t* __restrict__ Et,
    uint32_t* __restrict__ Ct)
{
    __shared__ uint32_t As[2][BM * ASTR];
    __shared__ uint32_t Bs[2][BK * BSTR_NN];

    const int b = blockIdx.z;
    const uint32_t* Ab = At + (size_t)b * SQ * SK;
    const uint32_t* Eb = Et + (size_t)b * SK * DIM;
    uint32_t* Cb = Ct + (size_t)b * SQ * DIM;

    const int mBase = blockIdx.y * BM;
    const int nBase = blockIdx.x * BN;
    const int tid = threadIdx.x;
    const int lane = tid & 31;
    const int w = tid >> 5;
    const int m0 = (w & 3) * 32;
    const int n0 = (w >> 2) * 64;

    float acc[2][8][4];
    #pragma unroll
    for (int i = 0; i < 2; i++)
        #pragma unroll
        for (int j = 0; j < 8; j++)
            #pragma unroll
            for (int q = 0; q < 4; q++) acc[i][j][q] = 0.f;

    const int ldr = tid >> 2;          // A: 0..63 rows
    const int ldc = (tid & 3) * 4;
    const int kr = tid >> 4;           // B: k-row 0..15
    const int nc = (tid & 15) * 4;     // B: n word col 0..60

    const uint32_t sA = (uint32_t)__cvta_generic_to_shared(&As[0][0]);
    const uint32_t sB = (uint32_t)__cvta_generic_to_shared(&Bs[0][0]);
    const uint32_t stageA = BM * ASTR * 4;
    const uint32_t stageB = BK * BSTR_NN * 4;
    const uint32_t dA0 = (ldr * ASTR + ldc) * 4;
    const uint32_t dA1 = ((ldr + 64) * ASTR + ldc) * 4;
    const uint32_t dB0 = (kr * BSTR_NN + nc) * 4;
    const uint32_t dB1 = (kr * BSTR_NN + nc + 64) * 4;

    {
        cp16(sA + dA0, Ab + (size_t)(mBase + ldr) * SK + ldc);
        cp16(sA + dA1, Ab + (size_t)(mBase + ldr + 64) * SK + ldc);
        cp16(sB + dB0, Eb + (size_t)kr * DIM + nBase + nc);
        cp16(sB + dB1, Eb + (size_t)kr * DIM + nBase + nc + 64);
        cp_commit();
    }

    const int NP = SK / BK;
    for (int i = 0; i < NP; i++) {
        cp_wait<0>();
        __syncthreads();
        if (i + 1 < NP) {
            int k = (i + 1) * BK;
            uint32_t bo = ((i + 1) & 1) ? 1u : 0u;
            cp16(sA + bo * stageA + dA0, Ab + (size_t)(mBase + ldr) * SK + k + ldc);
            cp16(sA + bo * stageA + dA1, Ab + (size_t)(mBase + ldr + 64) * SK + k + ldc);
            cp16(sB + bo * stageB + dB0, Eb + (size_t)(k + kr) * DIM + nBase + nc);
            cp16(sB + bo * stageB + dB1, Eb + (size_t)(k + kr) * DIM + nBase + nc + 64);
            cp_commit();
        }
        const uint32_t* Ac = As[i & 1];
        const uint32_t* Bc = Bs[i & 1];
        #pragma unroll
        for (int kc = 0; kc < BK; kc += 8) {
            uint32_t af[2][4], bf[8][2];
            #pragma unroll
            for (int mi = 0; mi < 2; mi++) {
                int r = m0 + mi * 16 + (lane >> 2);
                int c = kc + (lane & 3);
                af[mi][0] = Ac[r * ASTR + c];
                af[mi][1] = Ac[(r + 8) * ASTR + c];
                af[mi][2] = Ac[r * ASTR + c + 4];
                af[mi][3] = Ac[(r + 8) * ASTR + c + 4];
            }
            #pragma unroll
            for (int nj = 0; nj < 8; nj++) {
                int n = n0 + nj * 8 + (lane >> 2);
                int k = kc + (lane & 3);
                bf[nj][0] = Bc[k * BSTR_NN + n];
                bf[nj][1] = Bc[(k + 4) * BSTR_NN + n];
            }
            #pragma unroll
            for (int mi = 0; mi < 2; mi++)
                #pragma unroll
                for (int nj = 0; nj < 8; nj++)
                    mma_tf32(acc[mi][nj], af[mi][0], af[mi][1], af[mi][2], af[mi][3],
                             bf[nj][0], bf[nj][1]);
        }
    }

    #pragma unroll
    for (int mi = 0; mi < 2; mi++) {
        #pragma unroll
        for (int nj = 0; nj < 8; nj++) {
            int row = mBase + m0 + mi * 16 + (lane >> 2);
            int col = nBase + n0 + nj * 8 + (lane & 3) * 2;
            uint2 v0 = make_uint2(f2tf32(acc[mi][nj][0]), f2tf32(acc[mi][nj][1]));
            uint2 v1 = make_uint2(f2tf32(acc[mi][nj][2]), f2tf32(acc[mi][nj][3]));
            *(uint2*)(Cb + (size_t)row * DIM + col) = v0;
            *(uint2*)(Cb + (size_t)(row + 8) * DIM + col) = v1;
        }
    }
}

// ---------------------------------------------------------------------------
// Kernel 4: out = tanh([Qt|Ct] . Wt^T + b) * mask   (NT, K=1024)
// ---------------------------------------------------------------------------
__global__ __launch_bounds__(256, 2) void gemm_out_tc(
    const uint32_t* __restrict__ Qt, const uint32_t* __restrict__ Ct,
    const uint32_t* __restrict__ Wt,
    const float* __restrict__ bias, const float* __restrict__ mask,
    float* __restrict__ O)
{
    __shared__ uint32_t As[2][BM * ASTR];
    __shared__ uint32_t Bs[2][BN * BSTR];

    const int b = blockIdx.z;
    const uint32_t* Qb = Qt + (size_t)b * SQ * DIM;
    const uint32_t* Cb = Ct + (size_t)b * SQ * DIM;
    float* Ob = O + (size_t)b * SQ * DIM;

    const int mBase = blockIdx.y * BM;
    const int nBase = blockIdx.x * BN;
    const int tid = threadIdx.x;
    const int lane = tid & 31;
    const int w = tid >> 5;
    const int m0 = (w & 3) * 32;
    const int n0 = (w >> 2) * 64;

    float acc[2][8][4];
    #pragma unroll
    for (int i = 0; i < 2; i++)
        #pragma unroll
        for (int j = 0; j < 8; j++)
            #pragma unroll
            for (int q = 0; q < 4; q++) acc[i][j][q] = 0.f;

    const int ldr = tid >> 2;
    const int ldc = (tid & 3) * 4;

    const uint32_t sA = (uint32_t)__cvta_generic_to_shared(&As[0][0]);
    const uint32_t sB = (uint32_t)__cvta_generic_to_shared(&Bs[0][0]);
    const uint32_t stageA = BM * ASTR * 4;
    const uint32_t stageB = BN * BSTR * 4;
    const uint32_t dA0 = (ldr * ASTR + ldc) * 4;
    const uint32_t dA1 = ((ldr + 64) * ASTR + ldc) * 4;
    const uint32_t dB0 = (ldr * BSTR + ldc) * 4;
    const uint32_t dB1 = ((ldr + 64) * BSTR + ldc) * 4;

    {
        cp16(sA + dA0, Qb + (size_t)(mBase + ldr) * DIM + ldc);
        cp16(sA + dA1, Qb + (size_t)(mBase + ldr + 64) * DIM + ldc);
        cp16(sB + dB0, Wt + (size_t)(nBase + ldr) * DIM2 + ldc);
        cp16(sB + dB1, Wt + (size_t)(nBase + ldr + 64) * DIM2 + ldc);
        cp_commit();
    }

    const int NP = DIM2 / BK;  // 64
    for (int i = 0; i < NP; i++) {
        cp_wait<0>();
        __syncthreads();
        if (i + 1 < NP) {
            int k = (i + 1) * BK;
            const uint32_t* Asrc = (k < DIM) ? Qb : Cb;
            int kk = k & (DIM - 1);
            uint32_t bo = ((i + 1) & 1) ? 1u : 0u;
            cp16(sA + bo * stageA + dA0, Asrc + (size_t)(mBase + ldr) * DIM + kk + ldc);
            cp16(sA + bo * stageA + dA1, Asrc + (size_t)(mBase + ldr + 64) * DIM + kk + ldc);
            cp16(sB + bo * stageB + dB0, Wt + (size_t)(nBase + ldr) * DIM2 + k + ldc);
            cp16(sB + bo * stageB + dB1, Wt + (size_t)(nBase + ldr + 64) * DIM2 + k + ldc);
            cp_commit();
        }
        const uint32_t* Ac = As[i & 1];
        const uint32_t* Bc = Bs[i & 1];
        #pragma unroll
        for (int kc = 0; kc < BK; kc += 8) {
            uint32_t af[2][4], bf[8][2];
            #pragma unroll
            for (int mi = 0; mi < 2; mi++) {
                int r = m0 + mi * 16 + (lane >> 2);
                int c = kc + (lane & 3);
                af[mi][0] = Ac[r * ASTR + c];
                af[mi][1] = Ac[(r + 8) * ASTR + c];
                af[mi][2] = Ac[r * ASTR + c + 4];
                af[mi][3] = Ac[(r + 8) * ASTR + c + 4];
            }
            #pragma unroll
            for (int nj = 0; nj < 8; nj++) {
                int r = n0 + nj * 8 + (lane >> 2);
                int c = kc + (lane & 3);
                bf[nj][0] = Bc[r * BSTR + c];
                bf[nj][1] = Bc[r * BSTR + c + 4];
            }
            #pragma unroll
            for (int mi = 0; mi < 2; mi++)
                #pragma unroll
                for (int nj = 0; nj < 8; nj++)
                    mma_tf32(acc[mi][nj], af[mi][0], af[mi][1], af[mi][2], af[mi][3],
                             bf[nj][0], bf[nj][1]);
        }
    }

    #pragma unroll
    for (int mi = 0; mi < 2; mi++) {
        #pragma unroll
        for (int nj = 0; nj < 8; nj++) {
            int row = mBase + m0 + mi * 16 + (lane >> 2);
            int col = nBase + n0 + nj * 8 + (lane & 3) * 2;
            float b0 = bias[col], b1 = bias[col + 1];
            float mk0 = mask[(size_t)b * SQ + row];
            float mk1 = mask[(size_t)b * SQ + row + 8];
            *(float2*)(Ob + (size_t)row * DIM + col) =
                make_float2(tanhf(acc[mi][nj][0] + b0) * mk0,
                            tanhf(acc[mi][nj][1] + b1) * mk0);
            *(float2*)(Ob + (size_t)(row + 8) * DIM + col) =
                make_float2(tanhf(acc[mi][nj][2] + b0) * mk1,
                            tanhf(acc[mi][nj][3] + b1) * mk1);
        }
    }
}

// ---------------------------------------------------------------------------
extern "C" void kernel_launch(void* const* d_in, const int* in_sizes, int n_in,
                              void* d_out, int out_size)
{
    const float* Q    = (const float*)d_in[0];
    const float* E    = (const float*)d_in[1];
    const float* mask = (const float*)d_in[2];
    const float* W    = (const float*)d_in[3];
    const float* bias = (const float*)d_in[4];

    float* out = (float*)d_out;
    float* out_masked  = out;
    float* out_weights = out + (size_t)BATCH * SQ * DIM;

    uint32_t *Qt, *Et, *Wt, *At, *Ct;
    cudaGetSymbolAddress((void**)&Qt, g_Qt);
    cudaGetSymbolAddress((void**)&Et, g_Et);
    cudaGetSymbolAddress((void**)&Wt, g_Wt);
    cudaGetSymbolAddress((void**)&At, g_At);
    cudaGetSymbolAddress((void**)&Ct, g_Ct);

    // 0) convert inputs to tf32
    {
        int n4q = BATCH * SQ * DIM / 4;
        cvt_tf32_kernel<<<(n4q + 255) / 256, 256>>>((const float4*)Q, (uint4*)Qt, n4q);
        cvt_tf32_kernel<<<(n4q + 255) / 256, 256>>>((const float4*)E, (uint4*)Et, n4q);
        int n4w = DIM * DIM2 / 4;
        cvt_tf32_kernel<<<(n4w + 255) / 256, 256>>>((const float4*)W, (uint4*)Wt, n4w);
    }

    dim3 blk(256);
    dim3 grid(SK / BN, SQ / BM, BATCH);   // (4,4,32)

    gemm_scores_tc<<<grid, blk>>>(Qt, Et, out_weights);
    softmax_rows<<<BATCH * SQ, 256>>>(out_weights, At);
    gemm_ctx_tc<<<grid, blk>>>(At, Et, Ct);
    gemm_out_tc<<<grid, blk>>>(Qt, Ct, Wt, bias, mask, out_masked);
}

// round 7
// speedup vs baseline: 2.0874x; 1.7433x over previous
#include <cuda_runtime.h>
#include <math.h>
#include <stdint.h>

#define BATCH 32
#define SQ 512
#define SK 512
#define DIM 512
#define DIM2 1024
#define SCALE 0.044194173824159216f  // 1/sqrt(512)

// --- tiling: CTA 128x128, 4 warps of 64x64, BK=32, 3-stage cp.async ring ---
#define ASTR 36           // A smem row stride in words (32 + 4 pad)
#define BSTR 36           // B smem row stride (NT)
#define BSTR_NN 136       // B smem row stride (NN): 128 + 8 pad
#define NT_SBYTES (128 * ASTR * 4)       // 18432 per operand stage
#define NT_PAIR   (2 * NT_SBYTES)        // 36864
#define NT_SMEM   (3 * NT_PAIR)          // 110592
#define NN_BBYTES (32 * BSTR_NN * 4)     // 17408
#define NN_PAIR   (NT_SBYTES + NN_BBYTES)
#define NN_SMEM   (3 * NN_PAIR)          // 107520

// device-global tf32 scratch (no allocations)
__device__ uint32_t g_Qt[BATCH * SQ * DIM];
__device__ uint32_t g_Et[BATCH * SK * DIM];
__device__ uint32_t g_Wt[DIM * DIM2];
__device__ uint32_t g_At[BATCH * SQ * SK];
__device__ uint32_t g_Ct[BATCH * SQ * DIM];

__device__ __forceinline__ uint32_t f2tf32(float f) {
    uint32_t r;
    asm("cvt.rna.tf32.f32 %0, %1;" : "=r"(r) : "f"(f));
    return r;
}
__device__ __forceinline__ void cp16(uint32_t smem_dst, const void* gsrc) {
    asm volatile("cp.async.cg.shared.global [%0], [%1], 16;" :: "r"(smem_dst), "l"(gsrc));
}
__device__ __forceinline__ void cp_commit() { asm volatile("cp.async.commit_group;"); }
template <int N>
__device__ __forceinline__ void cp_wait() { asm volatile("cp.async.wait_group %0;" :: "n"(N)); }
__device__ __forceinline__ uint32_t smem_u32(const void* p) {
    uint32_t a;
    asm("{ .reg .u64 t; cvta.to.shared.u64 t, %1; cvt.u32.u64 %0, t; }" : "=r"(a) : "l"(p));
    return a;
}
__device__ __forceinline__ void mma_tf32(float c[4],
    uint32_t a0, uint32_t a1, uint32_t a2, uint32_t a3, uint32_t b0, uint32_t b1)
{
    asm volatile(
        "mma.sync.aligned.m16n8k8.row.col.f32.tf32.tf32.f32 "
        "{%0,%1,%2,%3}, {%4,%5,%6,%7}, {%8,%9}, {%0,%1,%2,%3};"
        : "+f"(c[0]), "+f"(c[1]), "+f"(c[2]), "+f"(c[3])
        : "r"(a0), "r"(a1), "r"(a2), "r"(a3), "r"(b0), "r"(b1));
}

// NT compute step on one stage: warp 64x64, 4 k-steps of k8
__device__ __forceinline__ void compute_nt(
    const uint32_t* As, const uint32_t* Bs, int m0, int n0, int lane, float acc[4][8][4])
{
    #pragma unroll
    for (int kc = 0; kc < 32; kc += 8) {
        uint32_t af[4][4], bf[8][2];
        #pragma unroll
        for (int mi = 0; mi < 4; mi++) {
            int r = m0 + mi * 16 + (lane >> 2);
            int c = kc + (lane & 3);
            af[mi][0] = As[r * ASTR + c];
            af[mi][1] = As[(r + 8) * ASTR + c];
            af[mi][2] = As[r * ASTR + c + 4];
            af[mi][3] = As[(r + 8) * ASTR + c + 4];
        }
        #pragma unroll
        for (int nj = 0; nj < 8; nj++) {
            int r = n0 + nj * 8 + (lane >> 2);
            int c = kc + (lane & 3);
            bf[nj][0] = Bs[r * BSTR + c];
            bf[nj][1] = Bs[r * BSTR + c + 4];
        }
        #pragma unroll
        for (int mi = 0; mi < 4; mi++)
            #pragma unroll
            for (int nj = 0; nj < 8; nj++)
                mma_tf32(acc[mi][nj], af[mi][0], af[mi][1], af[mi][2], af[mi][3],
                         bf[nj][0], bf[nj][1]);
    }
}

// ---------------------------------------------------------------------------
// Kernel 1: scores = SCALE * Qt . Et^T  (NT, K=512)
// ---------------------------------------------------------------------------
__global__ __launch_bounds__(128, 2) void tc_scores(
    const uint32_t* __restrict__ Qt, const uint32_t* __restrict__ Et,
    float* __restrict__ S)
{
    extern __shared__ uint32_t sm[];
    const int b = blockIdx.z, mBase = blockIdx.y * 128, nBase = blockIdx.x * 128;
    const uint32_t* Ab = Qt + (size_t)b * SQ * DIM + (size_t)mBase * DIM;
    const uint32_t* Bb = Et + (size_t)b * SK * DIM + (size_t)nBase * DIM;
    float* Sb = S + (size_t)b * SQ * SK;

    const int tid = threadIdx.x, lane = tid & 31, w = tid >> 5;
    const int m0 = (w & 1) * 64, n0 = (w >> 1) * 64;
    const int chunk = tid & 7, rg = tid >> 3;   // loader: 8 chunks x 16 row-groups
    const uint32_t sbase = smem_u32(sm);

    float acc[4][8][4];
    #pragma unroll
    for (int i = 0; i < 4; i++)
        #pragma unroll
        for (int j = 0; j < 8; j++)
            #pragma unroll
            for (int q = 0; q < 4; q++) acc[i][j][q] = 0.f;

    auto issue = [&](int p) {
        uint32_t st = sbase + (p % 3) * NT_PAIR;
        int k = p * 32;
        #pragma unroll
        for (int i = 0; i < 8; i++) {
            int row = rg + 16 * i;
            uint32_t d = (uint32_t)(row * ASTR + chunk * 4) * 4;
            cp16(st + d, Ab + (size_t)row * DIM + k + chunk * 4);
            cp16(st + NT_SBYTES + d, Bb + (size_t)row * DIM + k + chunk * 4);
        }
        cp_commit();
    };

    issue(0); issue(1);
    const int NP = 16;
    for (int p = 0; p < NP; p++) {
        if (p + 1 < NP) cp_wait<1>(); else cp_wait<0>();
        __syncthreads();
        if (p + 2 < NP) issue(p + 2);
        const uint32_t* As = sm + (p % 3) * (NT_PAIR / 4);
        compute_nt(As, As + NT_SBYTES / 4, m0, n0, lane, acc);
    }

    #pragma unroll
    for (int mi = 0; mi < 4; mi++)
        #pragma unroll
        for (int nj = 0; nj < 8; nj++) {
            int row = mBase + m0 + mi * 16 + (lane >> 2);
            int col = nBase + n0 + nj * 8 + (lane & 3) * 2;
            *(float2*)(Sb + (size_t)row * SK + col) =
                make_float2(acc[mi][nj][0] * SCALE, acc[mi][nj][1] * SCALE);
            *(float2*)(Sb + (size_t)(row + 8) * SK + col) =
                make_float2(acc[mi][nj][2] * SCALE, acc[mi][nj][3] * SCALE);
        }
}

// ---------------------------------------------------------------------------
// Kernel 3: ctx = At . Et  (NN, K=512) -> tf32 out
// ---------------------------------------------------------------------------
__global__ __launch_bounds__(128, 2) void tc_ctx(
    const uint32_t* __restrict__ At, const uint32_t* __restrict__ Et,
    uint32_t* __restrict__ Ct)
{
    extern __shared__ uint32_t sm[];
    const int b = blockIdx.z, mBase = blockIdx.y * 128, nBase = blockIdx.x * 128;
    const uint32_t* Ab = At + (size_t)b * SQ * SK + (size_t)mBase * SK;
    const uint32_t* Bb = Et + (size_t)b * SK * DIM + nBase;
    uint32_t* Cb = Ct + (size_t)b * SQ * DIM;

    const int tid = threadIdx.x, lane = tid & 31, w = tid >> 5;
    const int m0 = (w & 1) * 64, n0 = (w >> 1) * 64;
    const int chunk = tid & 7, rg = tid >> 3;          // A loader
    const int brow = tid >> 2, bch = tid & 3;          // B loader: 32 rows x 4 thr
    const uint32_t sbase = smem_u32(sm);

    float acc[4][8][4];
    #pragma unroll
    for (int i = 0; i < 4; i++)
        #pragma unroll
        for (int j = 0; j < 8; j++)
            #pragma unroll
            for (int q = 0; q < 4; q++) acc[i][j][q] = 0.f;

    auto issue = [&](int p) {
        uint32_t st = sbase + (p % 3) * NN_PAIR;
        int k = p * 32;
        #pragma unroll
        for (int i = 0; i < 8; i++) {
            int row = rg + 16 * i;
            cp16(st + (uint32_t)(row * ASTR + chunk * 4) * 4,
                 Ab + (size_t)row * SK + k + chunk * 4);
        }
        #pragma unroll
        for (int j = 0; j < 8; j++) {
            int nc = (bch + 4 * j) * 4;   // word col 0..124
            cp16(st + NT_SBYTES + (uint32_t)(brow * BSTR_NN + nc) * 4,
                 Bb + (size_t)(k + brow) * DIM + nc);
        }
        cp_commit();
    };

    issue(0); issue(1);
    const int NP = 16;
    for (int p = 0; p < NP; p++) {
        if (p + 1 < NP) cp_wait<1>(); else cp_wait<0>();
        __syncthreads();
        if (p + 2 < NP) issue(p + 2);
        const uint32_t* As = sm + (p % 3) * (NN_PAIR / 4);
        const uint32_t* Bs = As + NT_SBYTES / 4;
        #pragma unroll
        for (int kc = 0; kc < 32; kc += 8) {
            uint32_t af[4][4], bf[8][2];
            #pragma unroll
            for (int mi = 0; mi < 4; mi++) {
                int r = m0 + mi * 16 + (lane >> 2);
                int c = kc + (lane & 3);
                af[mi][0] = As[r * ASTR + c];
                af[mi][1] = As[(r + 8) * ASTR + c];
                af[mi][2] = As[r * ASTR + c + 4];
                af[mi][3] = As[(r + 8) * ASTR + c + 4];
            }
            #pragma unroll
            for (int nj = 0; nj < 8; nj++) {
                int n = n0 + nj * 8 + (lane >> 2);
                int k = kc + (lane & 3);
                bf[nj][0] = Bs[k * BSTR_NN + n];
                bf[nj][1] = Bs[(k + 4) * BSTR_NN + n];
            }
            #pragma unroll
            for (int mi = 0; mi < 4; mi++)
                #pragma unroll
                for (int nj = 0; nj < 8; nj++)
                    mma_tf32(acc[mi][nj], af[mi][0], af[mi][1], af[mi][2], af[mi][3],
                             bf[nj][0], bf[nj][1]);
        }
    }

    #pragma unroll
    for (int mi = 0; mi < 4; mi++)
        #pragma unroll
        for (int nj = 0; nj < 8; nj++) {
            int row = mBase + m0 + mi * 16 + (lane >> 2);
            int col = nBase + n0 + nj * 8 + (lane & 3) * 2;
            *(uint2*)(Cb + (size_t)row * DIM + col) =
                make_uint2(f2tf32(acc[mi][nj][0]), f2tf32(acc[mi][nj][1]));
            *(uint2*)(Cb + (size_t)(row + 8) * DIM + col) =
                make_uint2(f2tf32(acc[mi][nj][2]), f2tf32(acc[mi][nj][3]));
        }
}

// ---------------------------------------------------------------------------
// Kernel 4: out = tanh([Qt|Ct] . Wt^T + b) * mask  (NT, K=1024)
// ---------------------------------------------------------------------------
__global__ __launch_bounds__(128, 2) void tc_out(
    const uint32_t* __restrict__ Qt, const uint32_t* __restrict__ Ct,
    const uint32_t* __restrict__ Wt,
    const float* __restrict__ bias, const float* __restrict__ mask,
    float* __restrict__ O)
{
    extern __shared__ uint32_t sm[];
    const int b = blockIdx.z, mBase = blockIdx.y * 128, nBase = blockIdx.x * 128;
    const uint32_t* A0 = Qt + (size_t)b * SQ * DIM + (size_t)mBase * DIM;
    const uint32_t* A1 = Ct + (size_t)b * SQ * DIM + (size_t)mBase * DIM;
    const uint32_t* Bb = Wt + (size_t)nBase * DIM2;
    float* Ob = O + (size_t)b * SQ * DIM;

    const int tid = threadIdx.x, lane = tid & 31, w = tid >> 5;
    const int m0 = (w & 1) * 64, n0 = (w >> 1) * 64;
    const int chunk = tid & 7, rg = tid >> 3;
    const uint32_t sbase = smem_u32(sm);

    float acc[4][8][4];
    #pragma unroll
    for (int i = 0; i < 4; i++)
        #pragma unroll
        for (int j = 0; j < 8; j++)
            #pragma unroll
            for (int q = 0; q < 4; q++) acc[i][j][q] = 0.f;

    auto issue = [&](int p) {
        uint32_t st = sbase + (p % 3) * NT_PAIR;
        const uint32_t* Ap = (p < 16) ? A0 : A1;
        int ka = (p & 15) * 32;
        int kb = p * 32;
        #pragma unroll
        for (int i = 0; i < 8; i++) {
            int row = rg + 16 * i;
            uint32_t d = (uint32_t)(row * ASTR + chunk * 4) * 4;
            cp16(st + d, Ap + (size_t)row * DIM + ka + chunk * 4);
            cp16(st + NT_SBYTES + d, Bb + (size_t)row * DIM2 + kb + chunk * 4);
        }
        cp_commit();
    };

    issue(0); issue(1);
    const int NP = 32;
    for (int p = 0; p < NP; p++) {
        if (p + 1 < NP) cp_wait<1>(); else cp_wait<0>();
        __syncthreads();
        if (p + 2 < NP) issue(p + 2);
        const uint32_t* As = sm + (p % 3) * (NT_PAIR / 4);
        compute_nt(As, As + NT_SBYTES / 4, m0, n0, lane, acc);
    }

    #pragma unroll
    for (int mi = 0; mi < 4; mi++)
        #pragma unroll
        for (int nj = 0; nj < 8; nj++) {
            int row = mBase + m0 + mi * 16 + (lane >> 2);
            int col = nBase + n0 + nj * 8 + (lane & 3) * 2;
            float b0 = bias[col], b1 = bias[col + 1];
            float mk0 = mask[(size_t)b * SQ + row];
            float mk1 = mask[(size_t)b * SQ + row + 8];
            *(float2*)(Ob + (size_t)row * DIM + col) =
                make_float2(tanhf(acc[mi][nj][0] + b0) * mk0,
                            tanhf(acc[mi][nj][1] + b1) * mk0);
            *(float2*)(Ob + (size_t)(row + 8) * DIM + col) =
                make_float2(tanhf(acc[mi][nj][2] + b0) * mk1,
                            tanhf(acc[mi][nj][3] + b1) * mk1);
        }
}

// ---------------------------------------------------------------------------
// support kernels
// ---------------------------------------------------------------------------
__global__ __launch_bounds__(256) void cvt_tf32_kernel(
    const float4* __restrict__ in, uint4* __restrict__ out, int n4)
{
    int i = blockIdx.x * 256 + threadIdx.x;
    if (i < n4) {
        float4 v = in[i];
        out[i] = make_uint4(f2tf32(v.x), f2tf32(v.y), f2tf32(v.z), f2tf32(v.w));
    }
}

__global__ __launch_bounds__(256) void softmax_rows(
    float* __restrict__ S, uint32_t* __restrict__ At)
{
    const int row = blockIdx.x;
    float* p = S + (size_t)row * SK;
    uint32_t* pt = At + (size_t)row * SK;
    const int tid = threadIdx.x;

    float v0 = p[tid];
    float v1 = p[tid + 256];

    __shared__ float red[8];

    float m = fmaxf(v0, v1);
    #pragma unroll
    for (int o = 16; o > 0; o >>= 1) m = fmaxf(m, __shfl_xor_sync(0xffffffffu, m, o));
    if ((tid & 31) == 0) red[tid >> 5] = m;
    __syncthreads();
    m = red[0];
    #pragma unroll
    for (int i = 1; i < 8; i++) m = fmaxf(m, red[i]);

    float e0 = __expf(v0 - m);
    float e1 = __expf(v1 - m);

    float s = e0 + e1;
    #pragma unroll
    for (int o = 16; o > 0; o >>= 1) s += __shfl_xor_sync(0xffffffffu, s, o);
    __syncthreads();
    if ((tid & 31) == 0) red[tid >> 5] = s;
    __syncthreads();
    s = red[0];
    #pragma unroll
    for (int i = 1; i < 8; i++) s += red[i];

    float inv = 1.0f / s;
    float w0 = e0 * inv, w1 = e1 * inv;
    p[tid] = w0;
    p[tid + 256] = w1;
    pt[tid] = f2tf32(w0);
    pt[tid + 256] = f2tf32(w1);
}

// ---------------------------------------------------------------------------
extern "C" void kernel_launch(void* const* d_in, const int* in_sizes, int n_in,
                              void* d_out, int out_size)
{
    const float* Q    = (const float*)d_in[0];
    const float* E    = (const float*)d_in[1];
    const float* mask = (const float*)d_in[2];
    const float* W    = (const float*)d_in[3];
    const float* bias = (const float*)d_in[4];

    float* out = (float*)d_out;
    float* out_masked  = out;
    float* out_weights = out + (size_t)BATCH * SQ * DIM;

    uint32_t *Qt, *Et, *Wt, *At, *Ct;
    cudaGetSymbolAddress((void**)&Qt, g_Qt);
    cudaGetSymbolAddress((void**)&Et, g_Et);
    cudaGetSymbolAddress((void**)&Wt, g_Wt);
    cudaGetSymbolAddress((void**)&At, g_At);
    cudaGetSymbolAddress((void**)&Ct, g_Ct);

    cudaFuncSetAttribute(tc_scores, cudaFuncAttributeMaxDynamicSharedMemorySize, NT_SMEM);
    cudaFuncSetAttribute(tc_ctx, cudaFuncAttributeMaxDynamicSharedMemorySize, NN_SMEM);
    cudaFuncSetAttribute(tc_out, cudaFuncAttributeMaxDynamicSharedMemorySize, NT_SMEM);

    // 0) tf32 operand prep
    {
        int n4 = BATCH * SQ * DIM / 4;
        cvt_tf32_kernel<<<(n4 + 255) / 256, 256>>>((const float4*)Q, (uint4*)Qt, n4);
        cvt_tf32_kernel<<<(n4 + 255) / 256, 256>>>((const float4*)E, (uint4*)Et, n4);
        int n4w = DIM * DIM2 / 4;
        cvt_tf32_kernel<<<(n4w + 255) / 256, 256>>>((const float4*)W, (uint4*)Wt, n4w);
    }

    dim3 grid(4, 4, BATCH);
    tc_scores<<<grid, 128, NT_SMEM>>>(Qt, Et, out_weights);
    softmax_rows<<<BATCH * SQ, 256>>>(out_weights, At);
    tc_ctx<<<grid, 128, NN_SMEM>>>(At, Et, Ct);
    tc_out<<<grid, 128, NT_SMEM>>>(Qt, Ct, Wt, bias, mask, out_masked);
}

// round 11
// speedup vs baseline: 3.5993x; 1.7243x over previous
#include <cuda_runtime.h>
#include <cuda_fp16.h>
#include <math.h>
#include <stdint.h>

#define BATCH 32
#define SQ 512
#define SK 512
#define DIM 512
#define DIM2 1024
#define SCALE 0.044194173824159216f  // 1/sqrt(512)

// CTA 128x128, 4 warps of 64x64, BK=32 fp16, 3-stage cp.async ring.
// Smem rows: 64B (32 fp16), no pad; XOR swizzle chunk^=(row>>1)&3 (conflict-free
// for both cp.async store phases and ldmatrix read phases).
#define BK 32
#define STG_OP (128 * 64)          // 8192 B per operand stage
#define STG_PAIR (2 * STG_OP)      // 16384
#define SMEM_NT (3 * STG_PAIR)     // 49152 (= default 48KB limit, no opt-in)

// fp16 operand buffers (uint2 for 8B-aligned vector writes)
__device__ uint2 g_Qh[BATCH * SQ * DIM / 4];
__device__ uint2 g_Eh[BATCH * SK * DIM / 4];
__device__ uint2 g_EhT[BATCH * DIM * SK / 4];
__device__ uint2 g_Wh[DIM * DIM2 / 4];
__device__ uint2 g_Ah[BATCH * SQ * SK / 4];
__device__ uint2 g_Ch[BATCH * SQ * DIM / 4];

__device__ __forceinline__ uint32_t f2h2(float lo, float hi) {
    uint32_t r;
    asm("cvt.rn.f16x2.f32 %0, %1, %2;" : "=r"(r) : "f"(hi), "f"(lo));
    return r;
}
__device__ __forceinline__ void cp16(uint32_t smem_dst, const void* gsrc) {
    asm volatile("cp.async.cg.shared.global [%0], [%1], 16;" :: "r"(smem_dst), "l"(gsrc));
}
__device__ __forceinline__ void cp_commit() { asm volatile("cp.async.commit_group;"); }
template <int N>
__device__ __forceinline__ void cp_wait() { asm volatile("cp.async.wait_group %0;" :: "n"(N)); }
__device__ __forceinline__ uint32_t smem_u32(const void* p) {
    uint32_t a;
    asm("{ .reg .u64 t; cvta.to.shared.u64 t, %1; cvt.u32.u64 %0, t; }" : "=r"(a) : "l"(p));
    return a;
}
__device__ __forceinline__ void ldsm4(uint32_t& r0, uint32_t& r1, uint32_t& r2, uint32_t& r3,
                                      uint32_t a) {
    asm volatile("ldmatrix.sync.aligned.m8n8.x4.shared.b16 {%0,%1,%2,%3}, [%4];"
                 : "=r"(r0), "=r"(r1), "=r"(r2), "=r"(r3) : "r"(a));
}
__device__ __forceinline__ void mma_f16(float c[4], const uint32_t a[4],
                                        uint32_t b0, uint32_t b1) {
    asm volatile(
        "mma.sync.aligned.m16n8k16.row.col.f32.f16.f16.f32 "
        "{%0,%1,%2,%3}, {%4,%5,%6,%7}, {%8,%9}, {%0,%1,%2,%3};"
        : "+f"(c[0]), "+f"(c[1]), "+f"(c[2]), "+f"(c[3])
        : "r"(a[0]), "r"(a[1]), "r"(a[2]), "r"(a[3]), "r"(b0), "r"(b1));
}

// one stage of compute: warp 64x64, K=32 (two m16n8k16 k-steps)
__device__ __forceinline__ void compute_fp16(
    uint32_t abase, uint32_t bbase, int m0, int n0, int lane, float acc[4][8][4])
{
    const int q = lane >> 3;
    const int arof = (q & 1) * 8 + (lane & 7);   // A: q0/q2 row, q1/q3 row+8
    const int acq = q >> 1;                      //    q2/q3 chunk +1
    const int brof = (q >> 1) * 8 + (lane & 7);  // B: q2/q3 row+8
    const int bcq = q & 1;                       //    q1/q3 chunk +1
    #pragma unroll
    for (int kh = 0; kh < 2; kh++) {             // k = 0, 16 -> chunk base 0, 2
        const int cb = kh * 2;
        uint32_t a[4][4];
        #pragma unroll
        for (int mi = 0; mi < 4; mi++) {
            int row = m0 + mi * 16 + arof;
            uint32_t ad = abase + row * 64 + (((cb + acq) ^ ((row >> 1) & 3)) << 4);
            ldsm4(a[mi][0], a[mi][1], a[mi][2], a[mi][3], ad);
        }
        #pragma unroll
        for (int njp = 0; njp < 4; njp++) {
            int row = n0 + njp * 16 + brof;
            uint32_t bd = bbase + row * 64 + (((cb + bcq) ^ ((row >> 1) & 3)) << 4);
            uint32_t b0, b1, b2, b3;
            ldsm4(b0, b1, b2, b3, bd);
            #pragma unroll
            for (int mi = 0; mi < 4; mi++) {
                mma_f16(acc[mi][njp * 2], a[mi], b0, b1);
                mma_f16(acc[mi][njp * 2 + 1], a[mi], b2, b3);
            }
        }
    }
}

// ---------------------------------------------------------------------------
// Kernel 1: raw scores = Qh . Eh^T  (NT, K=512); SCALE applied in softmax
// ---------------------------------------------------------------------------
__global__ __launch_bounds__(128, 2) void hgemm_scores(
    const __half* __restrict__ Qh, const __half* __restrict__ Eh,
    float* __restrict__ S)
{
    extern __shared__ uint32_t sm[];
    const int b = blockIdx.z, mBase = blockIdx.y * 128, nBase = blockIdx.x * 128;
    const __half* Ab = Qh + (size_t)b * SQ * DIM + (size_t)mBase * DIM;
    const __half* Bb = Eh + (size_t)b * SK * DIM + (size_t)nBase * DIM;
    float* Sb = S + (size_t)b * SQ * SK;

    const int tid = threadIdx.x, lane = tid & 31, w = tid >> 5;
    const int m0 = (w & 1) * 64, n0 = (w >> 1) * 64;
    const int lc = tid & 3, lr = tid >> 2;   // loader: chunk 0-3, row 0-31 (+32i)
    const uint32_t sbase = smem_u32(sm);

    float acc[4][8][4];
    #pragma unroll
    for (int i = 0; i < 4; i++)
        #pragma unroll
        for (int j = 0; j < 8; j++)
            #pragma unroll
            for (int qq = 0; qq < 4; qq++) acc[i][j][qq] = 0.f;

    auto issue = [&](int p) {
        uint32_t st = sbase + (p % 3) * STG_PAIR;
        int k = p * BK;
        #pragma unroll
        for (int i = 0; i < 4; i++) {
            int row = lr + 32 * i;
            uint32_t sw = (uint32_t)(row * 64 + ((lc ^ ((row >> 1) & 3)) << 4));
            cp16(st + sw, Ab + (size_t)row * DIM + k + lc * 8);
            cp16(st + STG_OP + sw, Bb + (size_t)row * DIM + k + lc * 8);
        }
        cp_commit();
    };

    issue(0); issue(1);
    const int NP = 16;
    for (int p = 0; p < NP; p++) {
        if (p + 1 < NP) cp_wait<1>(); else cp_wait<0>();
        __syncthreads();
        if (p + 2 < NP) issue(p + 2);
        uint32_t ab = sbase + (p % 3) * STG_PAIR;
        compute_fp16(ab, ab + STG_OP, m0, n0, lane, acc);
    }

    #pragma unroll
    for (int mi = 0; mi < 4; mi++)
        #pragma unroll
        for (int nj = 0; nj < 8; nj++) {
            int row = mBase + m0 + mi * 16 + (lane >> 2);
            int col = nBase + n0 + nj * 8 + (lane & 3) * 2;
            *(float2*)(Sb + (size_t)row * SK + col) =
                make_float2(acc[mi][nj][0], acc[mi][nj][1]);
            *(float2*)(Sb + (size_t)(row + 8) * SK + col) =
                make_float2(acc[mi][nj][2], acc[mi][nj][3]);
        }
}

// ---------------------------------------------------------------------------
// Kernel 3: ctx = Ah . EhT^T  (NT, K=512) -> fp16 out
// ---------------------------------------------------------------------------
__global__ __launch_bounds__(128, 2) void hgemm_ctx(
    const __half* __restrict__ Ah, const __half* __restrict__ EhT,
    __half* __restrict__ Ch)
{
    extern __shared__ uint32_t sm[];
    const int b = blockIdx.z, mBase = blockIdx.y * 128, nBase = blockIdx.x * 128;
    const __half* Ab = Ah + (size_t)b * SQ * SK + (size_t)mBase * SK;
    const __half* Bb = EhT + (size_t)b * DIM * SK + (size_t)nBase * SK;
    __half* Cb = Ch + (size_t)b * SQ * DIM;

    const int tid = threadIdx.x, lane = tid & 31, w = tid >> 5;
    const int m0 = (w & 1) * 64, n0 = (w >> 1) * 64;
    const int lc = tid & 3, lr = tid >> 2;
    const uint32_t sbase = smem_u32(sm);

    float acc[4][8][4];
    #pragma unroll
    for (int i = 0; i < 4; i++)
        #pragma unroll
        for (int j = 0; j < 8; j++)
            #pragma unroll
            for (int qq = 0; qq < 4; qq++) acc[i][j][qq] = 0.f;

    auto issue = [&](int p) {
        uint32_t st = sbase + (p % 3) * STG_PAIR;
        int k = p * BK;
        #pragma unroll
        for (int i = 0; i < 4; i++) {
            int row = lr + 32 * i;
            uint32_t sw = (uint32_t)(row * 64 + ((lc ^ ((row >> 1) & 3)) << 4));
            cp16(st + sw, Ab + (size_t)row * SK + k + lc * 8);
            cp16(st + STG_OP + sw, Bb + (size_t)row * SK + k + lc * 8);
        }
        cp_commit();
    };

    issue(0); issue(1);
    const int NP = 16;
    for (int p = 0; p < NP; p++) {
        if (p + 1 < NP) cp_wait<1>(); else cp_wait<0>();
        __syncthreads();
        if (p + 2 < NP) issue(p + 2);
        uint32_t ab = sbase + (p % 3) * STG_PAIR;
        compute_fp16(ab, ab + STG_OP, m0, n0, lane, acc);
    }

    #pragma unroll
    for (int mi = 0; mi < 4; mi++)
        #pragma unroll
        for (int nj = 0; nj < 8; nj++) {
            int row = mBase + m0 + mi * 16 + (lane >> 2);
            int col = nBase + n0 + nj * 8 + (lane & 3) * 2;
            *(uint32_t*)(Cb + (size_t)row * DIM + col) = f2h2(acc[mi][nj][0], acc[mi][nj][1]);
            *(uint32_t*)(Cb + (size_t)(row + 8) * DIM + col) = f2h2(acc[mi][nj][2], acc[mi][nj][3]);
        }
}

// ---------------------------------------------------------------------------
// Kernel 4: out = tanh([Qh|Ch] . Wh^T + b) * mask  (NT, K=1024)
// ---------------------------------------------------------------------------
__global__ __launch_bounds__(128, 2) void hgemm_out(
    const __half* __restrict__ Qh, const __half* __restrict__ Ch,
    const __half* __restrict__ Wh,
    const float* __restrict__ bias, const float* __restrict__ mask,
    float* __restrict__ O)
{
    extern __shared__ uint32_t sm[];
    const int b = blockIdx.z, mBase = blockIdx.y * 128, nBase = blockIdx.x * 128;
    const __half* A0 = Qh + (size_t)b * SQ * DIM + (size_t)mBase * DIM;
    const __half* A1 = Ch + (size_t)b * SQ * DIM + (size_t)mBase * DIM;
    const __half* Bb = Wh + (size_t)nBase * DIM2;
    float* Ob = O + (size_t)b * SQ * DIM;

    const int tid = threadIdx.x, lane = tid & 31, w = tid >> 5;
    const int m0 = (w & 1) * 64, n0 = (w >> 1) * 64;
    const int lc = tid & 3, lr = tid >> 2;
    const uint32_t sbase = smem_u32(sm);

    float acc[4][8][4];
    #pragma unroll
    for (int i = 0; i < 4; i++)
        #pragma unroll
        for (int j = 0; j < 8; j++)
            #pragma unroll
            for (int qq = 0; qq < 4; qq++) acc[i][j][qq] = 0.f;

    auto issue = [&](int p) {
        uint32_t st = sbase + (p % 3) * STG_PAIR;
        const __half* Ap = (p < 16) ? A0 : A1;
        int ka = (p & 15) * BK;
        int kb = p * BK;
        #pragma unroll
        for (int i = 0; i < 4; i++) {
            int row = lr + 32 * i;
            uint32_t sw = (uint32_t)(row * 64 + ((lc ^ ((row >> 1) & 3)) << 4));
            cp16(st + sw, Ap + (size_t)row * DIM + ka + lc * 8);
            cp16(st + STG_OP + sw, Bb + (size_t)row * DIM2 + kb + lc * 8);
        }
        cp_commit();
    };

    issue(0); issue(1);
    const int NP = 32;
    for (int p = 0; p < NP; p++) {
        if (p + 1 < NP) cp_wait<1>(); else cp_wait<0>();
        __syncthreads();
        if (p + 2 < NP) issue(p + 2);
        uint32_t ab = sbase + (p % 3) * STG_PAIR;
        compute_fp16(ab, ab + STG_OP, m0, n0, lane, acc);
    }

    #pragma unroll
    for (int mi = 0; mi < 4; mi++)
        #pragma unroll
        for (int nj = 0; nj < 8; nj++) {
            int row = mBase + m0 + mi * 16 + (lane >> 2);
            int col = nBase + n0 + nj * 8 + (lane & 3) * 2;
            float b0 = bias[col], b1 = bias[col + 1];
            float mk0 = mask[(size_t)b * SQ + row];
            float mk1 = mask[(size_t)b * SQ + row + 8];
            *(float2*)(Ob + (size_t)row * DIM + col) =
                make_float2(tanhf(acc[mi][nj][0] + b0) * mk0,
                            tanhf(acc[mi][nj][1] + b1) * mk0);
            *(float2*)(Ob + (size_t)(row + 8) * DIM + col) =
                make_float2(tanhf(acc[mi][nj][2] + b0) * mk1,
                            tanhf(acc[mi][nj][3] + b1) * mk1);
        }
}

// ---------------------------------------------------------------------------
// support kernels
// ---------------------------------------------------------------------------
__global__ __launch_bounds__(256) void cvt_f2h(
    const float4* __restrict__ in, uint2* __restrict__ out, int n4)
{
    int i = blockIdx.x * 256 + threadIdx.x;
    if (i < n4) {
        float4 v = in[i];
        out[i] = make_uint2(f2h2(v.x, v.y), f2h2(v.z, v.w));
    }
}

// EhT[b][d][k] = fp16(E[b][k][d])
__global__ __launch_bounds__(256) void transpose_f2h(
    const float* __restrict__ E, __half* __restrict__ T)
{
    __shared__ __half tile[32][33];
    const int b = blockIdx.z;
    const int tx = threadIdx.x & 31, ty = threadIdx.x >> 5;  // 32x8
    const int d0 = blockIdx.x * 32, k0 = blockIdx.y * 32;
    #pragma unroll
    for (int i = 0; i < 4; i++)
        tile[ty + 8 * i][tx] =
            __float2half_rn(E[((size_t)b * SK + k0 + ty + 8 * i) * DIM + d0 + tx]);
    __syncthreads();
    #pragma unroll
    for (int i = 0; i < 4; i++)
        T[((size_t)b * DIM + d0 + ty + 8 * i) * SK + k0 + tx] = tile[tx][ty + 8 * i];
}

// softmax over raw scores: weights = softmax(raw * SCALE); fp32 + fp16 outputs
__global__ __launch_bounds__(256) void softmax_rows(
    float* __restrict__ S, __half* __restrict__ Ah)
{
    const int row = blockIdx.x;
    float* p = S + (size_t)row * SK;
    __half* ph = Ah + (size_t)row * SK;
    const int tid = threadIdx.x;

    float v0 = p[tid] * SCALE;
    float v1 = p[tid + 256] * SCALE;

    __shared__ float red[8];

    float m = fmaxf(v0, v1);
    #pragma unroll
    for (int o = 16; o > 0; o >>= 1) m = fmaxf(m, __shfl_xor_sync(0xffffffffu, m, o));
    if ((tid & 31) == 0) red[tid >> 5] = m;
    __syncthreads();
    m = red[0];
    #pragma unroll
    for (int i = 1; i < 8; i++) m = fmaxf(m, red[i]);

    float e0 = __expf(v0 - m);
    float e1 = __expf(v1 - m);

    float s = e0 + e1;
    #pragma unroll
    for (int o = 16; o > 0; o >>= 1) s += __shfl_xor_sync(0xffffffffu, s, o);
    __syncthreads();
    if ((tid & 31) == 0) red[tid >> 5] = s;
    __syncthreads();
    s = red[0];
    #pragma unroll
    for (int i = 1; i < 8; i++) s += red[i];

    float inv = 1.0f / s;
    float w0 = e0 * inv, w1 = e1 * inv;
    p[tid] = w0;
    p[tid + 256] = w1;
    ph[tid] = __float2half_rn(w0);
    ph[tid + 256] = __float2half_rn(w1);
}

// ---------------------------------------------------------------------------
extern "C" void kernel_launch(void* const* d_in, const int* in_sizes, int n_in,
                              void* d_out, int out_size)
{
    const float* Q    = (const float*)d_in[0];
    const float* E    = (const float*)d_in[1];
    const float* mask = (const float*)d_in[2];
    const float* W    = (const float*)d_in[3];
    const float* bias = (const float*)d_in[4];

    float* out = (float*)d_out;
    float* out_masked  = out;
    float* out_weights = out + (size_t)BATCH * SQ * DIM;

    void *pQ, *pE, *pET, *pW, *pA, *pC;
    cudaGetSymbolAddress(&pQ, g_Qh);
    cudaGetSymbolAddress(&pE, g_Eh);
    cudaGetSymbolAddress(&pET, g_EhT);
    cudaGetSymbolAddress(&pW, g_Wh);
    cudaGetSymbolAddress(&pA, g_Ah);
    cudaGetSymbolAddress(&pC, g_Ch);
    __half* Qh  = (__half*)pQ;
    __half* Eh  = (__half*)pE;
    __half* EhT = (__half*)pET;
    __half* Wh  = (__half*)pW;
    __half* Ah  = (__half*)pA;
    __half* Ch  = (__half*)pC;

    // 0) fp16 operand prep
    {
        int n4 = BATCH * SQ * DIM / 4;
        cvt_f2h<<<(n4 + 255) / 256, 256>>>((const float4*)Q, (uint2*)Qh, n4);
        cvt_f2h<<<(n4 + 255) / 256, 256>>>((const float4*)E, (uint2*)Eh, n4);
        int n4w = DIM * DIM2 / 4;
        cvt_f2h<<<(n4w + 255) / 256, 256>>>((const float4*)W, (uint2*)Wh, n4w);
        dim3 tg(DIM / 32, SK / 32, BATCH);
        transpose_f2h<<<tg, 256>>>(E, EhT);
    }

    dim3 grid(4, 4, BATCH);
    hgemm_scores<<<grid, 128, SMEM_NT>>>(Qh, Eh, out_weights);
    softmax_rows<<<BATCH * SQ, 256>>>(out_weights, Ah);
    hgemm_ctx<<<grid, 128, SMEM_NT>>>(Ah, EhT, Ch);
    hgemm_out<<<grid, 128, SMEM_NT>>>(Qh, Ch, Wh, bias, mask, out_masked);
}

// round 12
// speedup vs baseline: 4.0475x; 1.1245x over previous
#include <cuda_runtime.h>
#include <cuda_fp16.h>
#include <math.h>
#include <stdint.h>

#define BATCH 32
#define SQ 512
#define SK 512
#define DIM 512
#define DIM2 1024
#define SCALE 0.044194173824159216f  // 1/sqrt(512)

// CTA 128x128, 4 warps of 64x64, BK=32 fp16, 4-stage cp.async ring (wait<=2).
// A / NT-B smem rows: 64B (32 fp16), XOR swizzle chunk^=(row>>1)&3.
// ctx-B smem rows: 256B (128 fp16, k-major source), XOR swizzle chunk^=(k&7).
#define BK 32
#define STG_OP (128 * 64)          // 8192 B per operand stage
#define STG_PAIR (2 * STG_OP)      // 16384
#define SMEM_NT (4 * STG_PAIR)     // 65536 (needs opt-in, 2 CTAs/SM = 128KB)

// fp16 operand buffers
__device__ uint2 g_Qh[BATCH * SQ * DIM / 4];
__device__ uint2 g_Eh[BATCH * SK * DIM / 4];
__device__ uint2 g_Wh[DIM * DIM2 / 4];
__device__ uint2 g_Ah[BATCH * SQ * SK / 4];
__device__ uint2 g_Ch[BATCH * SQ * DIM / 4];

__device__ __forceinline__ uint32_t f2h2(float lo, float hi) {
    uint32_t r;
    asm("cvt.rn.f16x2.f32 %0, %1, %2;" : "=r"(r) : "f"(hi), "f"(lo));
    return r;
}
__device__ __forceinline__ void cp16(uint32_t smem_dst, const void* gsrc) {
    asm volatile("cp.async.cg.shared.global [%0], [%1], 16;" :: "r"(smem_dst), "l"(gsrc));
}
__device__ __forceinline__ void cp_commit() { asm volatile("cp.async.commit_group;"); }
template <int N>
__device__ __forceinline__ void cp_wait() { asm volatile("cp.async.wait_group %0;" :: "n"(N)); }
__device__ __forceinline__ uint32_t smem_u32(const void* p) {
    uint32_t a;
    asm("{ .reg .u64 t; cvta.to.shared.u64 t, %1; cvt.u32.u64 %0, t; }" : "=r"(a) : "l"(p));
    return a;
}
__device__ __forceinline__ void ldsm4(uint32_t& r0, uint32_t& r1, uint32_t& r2, uint32_t& r3,
                                      uint32_t a) {
    asm volatile("ldmatrix.sync.aligned.m8n8.x4.shared.b16 {%0,%1,%2,%3}, [%4];"
                 : "=r"(r0), "=r"(r1), "=r"(r2), "=r"(r3) : "r"(a));
}
__device__ __forceinline__ void ldsm4t(uint32_t& r0, uint32_t& r1, uint32_t& r2, uint32_t& r3,
                                       uint32_t a) {
    asm volatile("ldmatrix.sync.aligned.m8n8.x4.trans.shared.b16 {%0,%1,%2,%3}, [%4];"
                 : "=r"(r0), "=r"(r1), "=r"(r2), "=r"(r3) : "r"(a));
}
__device__ __forceinline__ void mma_f16(float c[4], const uint32_t a[4],
                                        uint32_t b0, uint32_t b1) {
    asm volatile(
        "mma.sync.aligned.m16n8k16.row.col.f32.f16.f16.f32 "
        "{%0,%1,%2,%3}, {%4,%5,%6,%7}, {%8,%9}, {%0,%1,%2,%3};"
        : "+f"(c[0]), "+f"(c[1]), "+f"(c[2]), "+f"(c[3])
        : "r"(a[0]), "r"(a[1]), "r"(a[2]), "r"(a[3]), "r"(b0), "r"(b1));
}

// NT compute: both operands [row][k] 64B rows
__device__ __forceinline__ void compute_fp16(
    uint32_t abase, uint32_t bbase, int m0, int n0, int lane, float acc[4][8][4])
{
    const int q = lane >> 3;
    const int arof = (q & 1) * 8 + (lane & 7);
    const int acq = q >> 1;
    const int brof = (q >> 1) * 8 + (lane & 7);
    const int bcq = q & 1;
    #pragma unroll
    for (int kh = 0; kh < 2; kh++) {
        const int cb = kh * 2;
        uint32_t a[4][4];
        #pragma unroll
        for (int mi = 0; mi < 4; mi++) {
            int row = m0 + mi * 16 + arof;
            uint32_t ad = abase + row * 64 + (((cb + acq) ^ ((row >> 1) & 3)) << 4);
            ldsm4(a[mi][0], a[mi][1], a[mi][2], a[mi][3], ad);
        }
        #pragma unroll
        for (int njp = 0; njp < 4; njp++) {
            int row = n0 + njp * 16 + brof;
            uint32_t bd = bbase + row * 64 + (((cb + bcq) ^ ((row >> 1) & 3)) << 4);
            uint32_t b0, b1, b2, b3;
            ldsm4(b0, b1, b2, b3, bd);
            #pragma unroll
            for (int mi = 0; mi < 4; mi++) {
                mma_f16(acc[mi][njp * 2], a[mi], b0, b1);
                mma_f16(acc[mi][njp * 2 + 1], a[mi], b2, b3);
            }
        }
    }
}

// ctx compute: A [q][k] 64B rows (non-trans), B [k][d] 256B rows via ldmatrix.trans
__device__ __forceinline__ void compute_ctx(
    uint32_t abase, uint32_t bbase, int m0, int n0, int lane, float acc[4][8][4])
{
    const int q = lane >> 3;
    const int l = lane & 7;
    const int arof = (q & 1) * 8 + l;
    const int acq = q >> 1;
    const int bko = (q & 1) * 8 + l;   // k-row within 16-half
    const int bcq = q >> 1;            // d-group +0 / +1
    #pragma unroll
    for (int kh = 0; kh < 2; kh++) {
        const int cb = kh * 2;
        uint32_t a[4][4];
        #pragma unroll
        for (int mi = 0; mi < 4; mi++) {
            int row = m0 + mi * 16 + arof;
            uint32_t ad = abase + row * 64 + (((cb + acq) ^ ((row >> 1) & 3)) << 4);
            ldsm4(a[mi][0], a[mi][1], a[mi][2], a[mi][3], ad);
        }
        #pragma unroll
        for (int njp = 0; njp < 4; njp++) {
            int krow = kh * 16 + bko;                    // 0..31
            int chunk = (n0 >> 3) + njp * 2 + bcq;       // d-group (16B chunks)
            uint32_t bd = bbase + krow * 256 + ((chunk ^ (krow & 7)) << 4);
            uint32_t b0, b1, b2, b3;
            ldsm4t(b0, b1, b2, b3, bd);
            #pragma unroll
            for (int mi = 0; mi < 4; mi++) {
                mma_f16(acc[mi][njp * 2], a[mi], b0, b1);
                mma_f16(acc[mi][njp * 2 + 1], a[mi], b2, b3);
            }
        }
    }
}

// ring wait: guarantee group p done, allow up to 2 newer groups in flight
#define RING_WAIT(p, NP)                               \
    do {                                               \
        if ((p) + 2 < (NP)) cp_wait<2>();              \
        else if ((p) + 1 < (NP)) cp_wait<1>();         \
        else cp_wait<0>();                             \
    } while (0)

// ---------------------------------------------------------------------------
// Kernel 1: raw scores = Qh . Eh^T  (NT, K=512); SCALE applied in softmax
// ---------------------------------------------------------------------------
__global__ __launch_bounds__(128, 2) void hgemm_scores(
    const __half* __restrict__ Qh, const __half* __restrict__ Eh,
    float* __restrict__ S)
{
    extern __shared__ uint32_t sm[];
    const int b = blockIdx.z, mBase = blockIdx.y * 128, nBase = blockIdx.x * 128;
    const __half* Ab = Qh + (size_t)b * SQ * DIM + (size_t)mBase * DIM;
    const __half* Bb = Eh + (size_t)b * SK * DIM + (size_t)nBase * DIM;
    float* Sb = S + (size_t)b * SQ * SK;

    const int tid = threadIdx.x, lane = tid & 31, w = tid >> 5;
    const int m0 = (w & 1) * 64, n0 = (w >> 1) * 64;
    const int lc = tid & 3, lr = tid >> 2;
    const uint32_t sbase = smem_u32(sm);

    float acc[4][8][4];
    #pragma unroll
    for (int i = 0; i < 4; i++)
        #pragma unroll
        for (int j = 0; j < 8; j++)
            #pragma unroll
            for (int qq = 0; qq < 4; qq++) acc[i][j][qq] = 0.f;

    auto issue = [&](int p) {
        uint32_t st = sbase + (p & 3) * STG_PAIR;
        int k = p * BK;
        #pragma unroll
        for (int i = 0; i < 4; i++) {
            int row = lr + 32 * i;
            uint32_t sw = (uint32_t)(row * 64 + ((lc ^ ((row >> 1) & 3)) << 4));
            cp16(st + sw, Ab + (size_t)row * DIM + k + lc * 8);
            cp16(st + STG_OP + sw, Bb + (size_t)row * DIM + k + lc * 8);
        }
        cp_commit();
    };

    issue(0); issue(1); issue(2);
    const int NP = 16;
    for (int p = 0; p < NP; p++) {
        RING_WAIT(p, NP);
        __syncthreads();
        if (p + 3 < NP) issue(p + 3);
        uint32_t ab = sbase + (p & 3) * STG_PAIR;
        compute_fp16(ab, ab + STG_OP, m0, n0, lane, acc);
    }

    #pragma unroll
    for (int mi = 0; mi < 4; mi++)
        #pragma unroll
        for (int nj = 0; nj < 8; nj++) {
            int row = mBase + m0 + mi * 16 + (lane >> 2);
            int col = nBase + n0 + nj * 8 + (lane & 3) * 2;
            *(float2*)(Sb + (size_t)row * SK + col) =
                make_float2(acc[mi][nj][0], acc[mi][nj][1]);
            *(float2*)(Sb + (size_t)(row + 8) * SK + col) =
                make_float2(acc[mi][nj][2], acc[mi][nj][3]);
        }
}

// ---------------------------------------------------------------------------
// Kernel 3: ctx = Ah . Eh  (A NT, B trans-ldmatrix on [k][d], K=512) -> fp16
// ---------------------------------------------------------------------------
__global__ __launch_bounds__(128, 2) void hgemm_ctx(
    const __half* __restrict__ Ah, const __half* __restrict__ Eh,
    __half* __restrict__ Ch)
{
    extern __shared__ uint32_t sm[];
    const int b = blockIdx.z, mBase = blockIdx.y * 128, nBase = blockIdx.x * 128;
    const __half* Ab = Ah + (size_t)b * SQ * SK + (size_t)mBase * SK;
    const __half* Bb = Eh + (size_t)b * SK * DIM + nBase;   // [k][d] slab
    __half* Cb = Ch + (size_t)b * SQ * DIM;

    const int tid = threadIdx.x, lane = tid & 31, w = tid >> 5;
    const int m0 = (w & 1) * 64, n0 = (w >> 1) * 64;
    const int lc = tid & 3, lr = tid >> 2;       // A loader
    const int bkr = tid >> 2, bcb = tid & 3;     // B loader: k-row 0..31, chunk base
    const uint32_t sbase = smem_u32(sm);

    float acc[4][8][4];
    #pragma unroll
    for (int i = 0; i < 4; i++)
        #pragma unroll
        for (int j = 0; j < 8; j++)
            #pragma unroll
            for (int qq = 0; qq < 4; qq++) acc[i][j][qq] = 0.f;

    auto issue = [&](int p) {
        uint32_t st = sbase + (p & 3) * STG_PAIR;
        int k = p * BK;
        #pragma unroll
        for (int i = 0; i < 4; i++) {
            int row = lr + 32 * i;
            uint32_t sw = (uint32_t)(row * 64 + ((lc ^ ((row >> 1) & 3)) << 4));
            cp16(st + sw, Ab + (size_t)row * SK + k + lc * 8);
        }
        #pragma unroll
        for (int j = 0; j < 4; j++) {
            int chunk = bcb + j * 4;    // 0..15 (d-chunk of 8 fp16)
            uint32_t sw = (uint32_t)(bkr * 256 + ((chunk ^ (bkr & 7)) << 4));
            cp16(st + STG_OP + sw, Bb + (size_t)(k + bkr) * DIM + chunk * 8);
        }
        cp_commit();
    };

    issue(0); issue(1); issue(2);
    const int NP = 16;
    for (int p = 0; p < NP; p++) {
        RING_WAIT(p, NP);
        __syncthreads();
        if (p + 3 < NP) issue(p + 3);
        uint32_t ab = sbase + (p & 3) * STG_PAIR;
        compute_ctx(ab, ab + STG_OP, m0, n0, lane, acc);
    }

    #pragma unroll
    for (int mi = 0; mi < 4; mi++)
        #pragma unroll
        for (int nj = 0; nj < 8; nj++) {
            int row = mBase + m0 + mi * 16 + (lane >> 2);
            int col = nBase + n0 + nj * 8 + (lane & 3) * 2;
            *(uint32_t*)(Cb + (size_t)row * DIM + col) = f2h2(acc[mi][nj][0], acc[mi][nj][1]);
            *(uint32_t*)(Cb + (size_t)(row + 8) * DIM + col) = f2h2(acc[mi][nj][2], acc[mi][nj][3]);
        }
}

// ---------------------------------------------------------------------------
// Kernel 4: out = tanh([Qh|Ch] . Wh^T + b) * mask  (NT, K=1024)
// ---------------------------------------------------------------------------
__global__ __launch_bounds__(128, 2) void hgemm_out(
    const __half* __restrict__ Qh, const __half* __restrict__ Ch,
    const __half* __restrict__ Wh,
    const float* __restrict__ bias, const float* __restrict__ mask,
    float* __restrict__ O)
{
    extern __shared__ uint32_t sm[];
    const int b = blockIdx.z, mBase = blockIdx.y * 128, nBase = blockIdx.x * 128;
    const __half* A0 = Qh + (size_t)b * SQ * DIM + (size_t)mBase * DIM;
    const __half* A1 = Ch + (size_t)b * SQ * DIM + (size_t)mBase * DIM;
    const __half* Bb = Wh + (size_t)nBase * DIM2;
    float* Ob = O + (size_t)b * SQ * DIM;

    const int tid = threadIdx.x, lane = tid & 31, w = tid >> 5;
    const int m0 = (w & 1) * 64, n0 = (w >> 1) * 64;
    const int lc = tid & 3, lr = tid >> 2;
    const uint32_t sbase = smem_u32(sm);

    float acc[4][8][4];
    #pragma unroll
    for (int i = 0; i < 4; i++)
        #pragma unroll
        for (int j = 0; j < 8; j++)
            #pragma unroll
            for (int qq = 0; qq < 4; qq++) acc[i][j][qq] = 0.f;

    auto issue = [&](int p) {
        uint32_t st = sbase + (p & 3) * STG_PAIR;
        const __half* Ap = (p < 16) ? A0 : A1;
        int ka = (p & 15) * BK;
        int kb = p * BK;
        #pragma unroll
        for (int i = 0; i < 4; i++) {
            int row = lr + 32 * i;
            uint32_t sw = (uint32_t)(row * 64 + ((lc ^ ((row >> 1) & 3)) << 4));
            cp16(st + sw, Ap + (size_t)row * DIM + ka + lc * 8);
            cp16(st + STG_OP + sw, Bb + (size_t)row * DIM2 + kb + lc * 8);
        }
        cp_commit();
    };

    issue(0); issue(1); issue(2);
    const int NP = 32;
    for (int p = 0; p < NP; p++) {
        RING_WAIT(p, NP);
        __syncthreads();
        if (p + 3 < NP) issue(p + 3);
        uint32_t ab = sbase + (p & 3) * STG_PAIR;
        compute_fp16(ab, ab + STG_OP, m0, n0, lane, acc);
    }

    #pragma unroll
    for (int mi = 0; mi < 4; mi++)
        #pragma unroll
        for (int nj = 0; nj < 8; nj++) {
            int row = mBase + m0 + mi * 16 + (lane >> 2);
            int col = nBase + n0 + nj * 8 + (lane & 3) * 2;
            float b0 = bias[col], b1 = bias[col + 1];
            float mk0 = mask[(size_t)b * SQ + row];
            float mk1 = mask[(size_t)b * SQ + row + 8];
            *(float2*)(Ob + (size_t)row * DIM + col) =
                make_float2(tanhf(acc[mi][nj][0] + b0) * mk0,
                            tanhf(acc[mi][nj][1] + b1) * mk0);
            *(float2*)(Ob + (size_t)(row + 8) * DIM + col) =
                make_float2(tanhf(acc[mi][nj][2] + b0) * mk1,
                            tanhf(acc[mi][nj][3] + b1) * mk1);
        }
}

// ---------------------------------------------------------------------------
// support kernels
// ---------------------------------------------------------------------------
__global__ __launch_bounds__(256) void cvt_f2h(
    const float4* __restrict__ in, uint2* __restrict__ out, int n4)
{
    int i = blockIdx.x * 256 + threadIdx.x;
    if (i < n4) {
        float4 v = in[i];
        out[i] = make_uint2(f2h2(v.x, v.y), f2h2(v.z, v.w));
    }
}

// softmax over raw scores (vectorized): weights = softmax(raw * SCALE)
__global__ __launch_bounds__(128) void softmax_rows(
    float* __restrict__ S, __half* __restrict__ Ah)
{
    const int row = blockIdx.x;
    float* p = S + (size_t)row * SK;
    __half* ph = Ah + (size_t)row * SK;
    const int tid = threadIdx.x;

    float4 v = *(float4*)(p + tid * 4);
    v.x *= SCALE; v.y *= SCALE; v.z *= SCALE; v.w *= SCALE;

    __shared__ float red[4];

    float m = fmaxf(fmaxf(v.x, v.y), fmaxf(v.z, v.w));
    #pragma unroll
    for (int o = 16; o > 0; o >>= 1) m = fmaxf(m, __shfl_xor_sync(0xffffffffu, m, o));
    if ((tid & 31) == 0) red[tid >> 5] = m;
    __syncthreads();
    m = fmaxf(fmaxf(red[0], red[1]), fmaxf(red[2], red[3]));

    float4 e;
    e.x = __expf(v.x - m); e.y = __expf(v.y - m);
    e.z = __expf(v.z - m); e.w = __expf(v.w - m);

    float s = (e.x + e.y) + (e.z + e.w);
    #pragma unroll
    for (int o = 16; o > 0; o >>= 1) s += __shfl_xor_sync(0xffffffffu, s, o);
    __syncthreads();
    if ((tid & 31) == 0) red[tid >> 5] = s;
    __syncthreads();
    s = (red[0] + red[1]) + (red[2] + red[3]);

    float inv = 1.0f / s;
    e.x *= inv; e.y *= inv; e.z *= inv; e.w *= inv;
    *(float4*)(p + tid * 4) = e;
    *(uint2*)(ph + tid * 4) = make_uint2(f2h2(e.x, e.y), f2h2(e.z, e.w));
}

// ---------------------------------------------------------------------------
extern "C" void kernel_launch(void* const* d_in, const int* in_sizes, int n_in,
                              void* d_out, int out_size)
{
    const float* Q    = (const float*)d_in[0];
    const float* E    = (const float*)d_in[1];
    const float* mask = (const float*)d_in[2];
    const float* W    = (const float*)d_in[3];
    const float* bias = (const float*)d_in[4];

    float* out = (float*)d_out;
    float* out_masked  = out;
    float* out_weights = out + (size_t)BATCH * SQ * DIM;

    void *pQ, *pE, *pW, *pA, *pC;
    cudaGetSymbolAddress(&pQ, g_Qh);
    cudaGetSymbolAddress(&pE, g_Eh);
    cudaGetSymbolAddress(&pW, g_Wh);
    cudaGetSymbolAddress(&pA, g_Ah);
    cudaGetSymbolAddress(&pC, g_Ch);
    __half* Qh = (__half*)pQ;
    __half* Eh = (__half*)pE;
    __half* Wh = (__half*)pW;
    __half* Ah = (__half*)pA;
    __half* Ch = (__half*)pC;

    // 64KB dynamic smem opt-in (idempotent)
    cudaFuncSetAttribute(hgemm_scores, cudaFuncAttributeMaxDynamicSharedMemorySize, SMEM_NT);
    cudaFuncSetAttribute(hgemm_ctx, cudaFuncAttributeMaxDynamicSharedMemorySize, SMEM_NT);
    cudaFuncSetAttribute(hgemm_out, cudaFuncAttributeMaxDynamicSharedMemorySize, SMEM_NT);

    // 0) fp16 operand prep (no transpose needed anymore)
    {
        int n4 = BATCH * SQ * DIM / 4;
        cvt_f2h<<<(n4 + 255) / 256, 256>>>((const float4*)Q, (uint2*)Qh, n4);
        cvt_f2h<<<(n4 + 255) / 256, 256>>>((const float4*)E, (uint2*)Eh, n4);
        int n4w = DIM * DIM2 / 4;
        cvt_f2h<<<(n4w + 255) / 256, 256>>>((const float4*)W, (uint2*)Wh, n4w);
    }

    dim3 grid(4, 4, BATCH);
    hgemm_scores<<<grid, 128, SMEM_NT>>>(Qh, Eh, out_weights);
    softmax_rows<<<BATCH * SQ, 128>>>(out_weights, Ah);
    hgemm_ctx<<<grid, 128, SMEM_NT>>>(Ah, Eh, Ch);
    hgemm_out<<<grid, 128, SMEM_NT>>>(Qh, Ch, Wh, bias, mask, out_masked);
}